// round 15
// baseline (speedup 1.0000x reference)
#include <cuda_runtime.h>
#include <cuda_bf16.h>
#include <cuda_fp16.h>
#include <cstdint>

#define NP 100000
#define NA 50000
#define EPP 1600000
#define EAP 800000
#define EPA 800000

// ---------------- scratch ----------------------------------------------------
__device__ __align__(16) __half g_hs0[NP * 128];   // layer-1 per-relation feats
__device__ __align__(16) __half g_hs1[NA * 128];
__device__ __align__(16) __half g_hs2[NP * 128];
__device__ __align__(16) __half g_hs0b[NP * 64];   // layer-2 (separate: no WAR)
__device__ __align__(16) __half g_hs1b[NA * 64];
__device__ __align__(16) __half g_hs2b[NP * 64];
__device__ __align__(16) float g_es[3 * NP * 8];
__device__ __align__(16) float g_ed[3 * NP * 8];
__device__ __align__(16) float g_esb[3 * NP * 8];
__device__ __align__(16) float g_edb[3 * NP * 8];
__device__ __align__(16) float g_accp[NP * 128];
__device__ __align__(16) float g_acca[NA * 128];
__device__ __align__(16) float g_vd1[3 * 512];
__device__ __align__(16) float g_vd2[3 * 512];
// CSR scratch
__device__ int g_off_pp[NP + 1];
__device__ int g_off_ap[NP + 1];
__device__ int g_off_pa[NA + 1];
__device__ int g_srt[EPP + EAP + EPA];
__device__ int g_writer[NP + NP + NA];

// ---------------- helpers ----------------------------------------------------
__device__ __forceinline__ uint32_t tf32(float x) {
    uint32_t r;
    asm("cvt.rna.tf32.f32 %0, %1;" : "=r"(r) : "f"(x));
    return r;
}
__device__ __forceinline__ void mma_tf32(float* d, const uint32_t* a, const uint32_t* b) {
    asm("mma.sync.aligned.m16n8k8.row.col.f32.tf32.tf32.f32 "
        "{%0,%1,%2,%3},{%4,%5,%6,%7},{%8,%9},{%0,%1,%2,%3};"
        : "+f"(d[0]), "+f"(d[1]), "+f"(d[2]), "+f"(d[3])
        : "r"(a[0]), "r"(a[1]), "r"(a[2]), "r"(a[3]), "r"(b[0]), "r"(b[1]));
}

// ---------------- batched CSR build -------------------------------------------
__global__ void count3(const int* __restrict__ d0, const int* __restrict__ d1,
                       const int* __restrict__ d2, int* __restrict__ o0,
                       int* __restrict__ o1, int* __restrict__ o2) {
    int i = blockIdx.x * blockDim.x + threadIdx.x;
    if (i < EPP) atomicAdd(&o0[d0[i] + 1], 1);
    else if (i < EPP + EAP) atomicAdd(&o1[d1[i - EPP] + 1], 1);
    else if (i < EPP + EAP + EPA) atomicAdd(&o2[d2[i - EPP - EAP] + 1], 1);
}
__device__ void scan_one(int* __restrict__ off, int* __restrict__ writer, int n, int nw) {
    __shared__ int ssum[1024];
    int tid = threadIdx.x;
    int running = 0;
    for (int base = 0; base < n; base += 4096) {
        int idx = base + tid * 4;
        int v0 = idx + 0 < n ? off[idx + 0] : 0;
        int v1 = idx + 1 < n ? off[idx + 1] : 0;
        int v2 = idx + 2 < n ? off[idx + 2] : 0;
        int v3 = idx + 3 < n ? off[idx + 3] : 0;
        int p0 = v0, p1 = p0 + v1, p2 = p1 + v2, p3 = p2 + v3;
        ssum[tid] = p3;
        __syncthreads();
        for (int o = 1; o < 1024; o <<= 1) {
            int val = 0;
            if (tid >= o) val = ssum[tid - o];
            __syncthreads();
            if (tid >= o) ssum[tid] += val;
            __syncthreads();
        }
        int excl = running + (tid ? ssum[tid - 1] : 0);
        int total = ssum[1023];
        __syncthreads();
        int s0 = excl + p0, s1 = excl + p1, s2 = excl + p2, s3 = excl + p3;
        if (idx + 0 < n) { off[idx + 0] = s0; if (idx + 0 < nw) writer[idx + 0] = s0; }
        if (idx + 1 < n) { off[idx + 1] = s1; if (idx + 1 < nw) writer[idx + 1] = s1; }
        if (idx + 2 < n) { off[idx + 2] = s2; if (idx + 2 < nw) writer[idx + 2] = s2; }
        if (idx + 3 < n) { off[idx + 3] = s3; if (idx + 3 < nw) writer[idx + 3] = s3; }
        running += total;
    }
}
__global__ void __launch_bounds__(1024)
scan3(int* __restrict__ o0, int* __restrict__ o1, int* __restrict__ o2,
      int* __restrict__ writer) {
    if (blockIdx.x == 0)      scan_one(o0, writer, NP + 1, NP);
    else if (blockIdx.x == 1) scan_one(o1, writer + NP, NP + 1, NP);
    else                      scan_one(o2, writer + 2 * NP, NA + 1, NA);
}
__global__ void scatter3(const int* __restrict__ s0, const int* __restrict__ d0,
                         const int* __restrict__ s1, const int* __restrict__ d1,
                         const int* __restrict__ s2, const int* __restrict__ d2,
                         int* __restrict__ writer, int* __restrict__ srt) {
    int i = blockIdx.x * blockDim.x + threadIdx.x;
    if (i < EPP) {
        int pos = atomicAdd(&writer[d0[i]], 1);
        srt[pos] = s0[i];
    } else if (i < EPP + EAP) {
        int e = i - EPP;
        int pos = atomicAdd(&writer[NP + d1[e]], 1);
        srt[EPP + pos] = s1[e];
    } else if (i < EPP + EAP + EPA) {
        int e = i - EPP - EAP;
        int pos = atomicAdd(&writer[2 * NP + d2[e]], 1);
        srt[EPP + EAP + pos] = s2[e];
    }
}

// ---------------- vd folding ---------------------------------------------------
__global__ void compute_vd(const float* __restrict__ Wd1, const float* __restrict__ ad1,
                           const float* __restrict__ Wd2, const float* __restrict__ ad2,
                           float* __restrict__ vd1, float* __restrict__ vd2) {
    int i = blockIdx.x * blockDim.x + threadIdx.x;
    if (i >= 2 * 3 * 128 * 4) return;
    int layer = i >= 3 * 128 * 4;
    int ii = i - layer * 3 * 128 * 4;
    int h = ii & 3;
    int f = (ii >> 2) & 127;
    int r = ii >> 9;
    int D = layer ? 64 : 128;
    int C = D / 4;
    const float* W = (layer ? Wd2 : Wd1) + (size_t)r * 128 * D + (size_t)f * D + h * C;
    const float* a = (layer ? ad2 : ad1) + r * 4 * C + h * C;
    float s = 0.f;
    for (int c = 0; c < C; c++) s += W[c] * a[c];
    (layer ? vd2 : vd1)[r * 512 + f * 4 + h] = s;
}

// ---------------- tf32 MMA GEMM + es epilogue + fused ed -----------------------
template <int CC, int NED>
__global__ void __launch_bounds__(256)
mma_es(const float* __restrict__ A, const float* __restrict__ B,
       __half* __restrict__ C, float* __restrict__ es,
       const float* __restrict__ a_s,
       const float* __restrict__ vdA, const float* __restrict__ vdB,
       float* __restrict__ edA, float* __restrict__ edB,
       int M, int N) {
    const int K = 128;
    const int BKc = 16;
    __shared__ __align__(16) float As[2][128][BKc + 4];
    __shared__ __align__(16) float Bs[2][BKc][64 + 8];
    __shared__ __align__(16) float vds[128][8];
    int tid = threadIdx.x;
    int lane = tid & 31, wid = tid >> 5;
    int wm = wid & 3, wn = wid >> 2;
    int g = lane >> 2, tig = lane & 3;
    int m0 = blockIdx.y * 128, n0 = blockIdx.x * 64;

    if (NED > 0) {
        for (int i = tid; i < 1024; i += 256) {
            int k = i >> 3, j = i & 7;
            float v = 0.f;
            if (j < 4) v = vdA[k * 4 + j];
            else if (NED == 2) v = vdB[k * 4 + (j - 4)];
            vds[k][j] = v;
        }
    }

    float cfr[2][4][4];
#pragma unroll
    for (int mt = 0; mt < 2; mt++)
#pragma unroll
        for (int nt = 0; nt < 4; nt++)
#pragma unroll
            for (int q = 0; q < 4; q++) cfr[mt][nt][q] = 0.f;
    float edf[2][4];
#pragma unroll
    for (int mt = 0; mt < 2; mt++)
#pragma unroll
        for (int q = 0; q < 4; q++) edf[mt][q] = 0.f;
    bool do_ed = (NED > 0) && (wn == 0) && (blockIdx.x == 0);

    int aRow = tid >> 1, aK = (tid & 1) * 8;
    int bRow = tid >> 4, bC = (tid & 15) * 4;

    float4 ra0, ra1, rb;
    auto loadg = [&](int k0) {
        int m = m0 + aRow;
        if (m < M) {
            ra0 = *(const float4*)(A + (size_t)m * K + k0 + aK);
            ra1 = *(const float4*)(A + (size_t)m * K + k0 + aK + 4);
        } else {
            ra0 = make_float4(0.f, 0.f, 0.f, 0.f);
            ra1 = ra0;
        }
        rb = *(const float4*)(B + (size_t)(k0 + bRow) * N + n0 + bC);
    };
    auto stores = [&](int buf) {
        *(float4*)&As[buf][aRow][aK] = ra0;
        *(float4*)&As[buf][aRow][aK + 4] = ra1;
        *(float4*)&Bs[buf][bRow][bC] = rb;
    };

    loadg(0);
    stores(0);
    __syncthreads();

#pragma unroll 1
    for (int c = 0; c < 8; c++) {
        if (c + 1 < 8) loadg((c + 1) * BKc);
        int buf = c & 1;
#pragma unroll
        for (int kk = 0; kk < BKc; kk += 8) {
            uint32_t af[2][4], bf[4][2];
#pragma unroll
            for (int mt = 0; mt < 2; mt++) {
                int rm = wm * 32 + mt * 16;
                af[mt][0] = tf32(As[buf][rm + g][kk + tig]);
                af[mt][1] = tf32(As[buf][rm + g + 8][kk + tig]);
                af[mt][2] = tf32(As[buf][rm + g][kk + tig + 4]);
                af[mt][3] = tf32(As[buf][rm + g + 8][kk + tig + 4]);
            }
#pragma unroll
            for (int nt = 0; nt < 4; nt++) {
                int cn = wn * 32 + nt * 8;
                bf[nt][0] = tf32(Bs[buf][kk + tig][cn + g]);
                bf[nt][1] = tf32(Bs[buf][kk + tig + 4][cn + g]);
            }
#pragma unroll
            for (int mt = 0; mt < 2; mt++)
#pragma unroll
                for (int nt = 0; nt < 4; nt++)
                    mma_tf32(cfr[mt][nt], af[mt], bf[nt]);
            if (do_ed) {
                uint32_t bvd[2];
                int kg = c * BKc + kk;
                bvd[0] = tf32(vds[kg + tig][g]);
                bvd[1] = tf32(vds[kg + tig + 4][g]);
                mma_tf32(edf[0], af[0], bvd);
                mma_tf32(edf[1], af[1], bvd);
            }
        }
        if (c + 1 < 8) stores((c + 1) & 1);
        __syncthreads();
    }

    if (do_ed) {
        auto edst = [&](int m, int col, float v) {
            int rel = col >> 2;
            if (rel == 1 && NED < 2) return;
            int h = col & 3;
            float* dst = rel ? edB : edA;
            if (m < M)
                *(float2*)(dst + m * 8 + h * 2) =
                    make_float2(__expf(v), __expf(0.2f * v));
        };
#pragma unroll
        for (int mt = 0; mt < 2; mt++) {
            int m_lo = m0 + wm * 32 + mt * 16 + g;
            int m_hi = m_lo + 8;
            edst(m_lo, 2 * tig + 0, edf[mt][0]);
            edst(m_lo, 2 * tig + 1, edf[mt][1]);
            edst(m_hi, 2 * tig + 0, edf[mt][2]);
            edst(m_hi, 2 * tig + 1, edf[mt][3]);
        }
    }

    {
        constexpr int NH = 32 / CC;
        float pl[2][NH], ph[2][NH];
#pragma unroll
        for (int mt = 0; mt < 2; mt++)
#pragma unroll
            for (int nh = 0; nh < NH; nh++) { pl[mt][nh] = 0.f; ph[mt][nh] = 0.f; }
#pragma unroll
        for (int nt = 0; nt < 4; nt++) {
            int nh = (nt * 8) / CC;
            float w0 = __ldg(&a_s[n0 + wn * 32 + nt * 8 + 2 * tig]);
            float w1 = __ldg(&a_s[n0 + wn * 32 + nt * 8 + 2 * tig + 1]);
#pragma unroll
            for (int mt = 0; mt < 2; mt++) {
                pl[mt][nh] += cfr[mt][nt][0] * w0 + cfr[mt][nt][1] * w1;
                ph[mt][nh] += cfr[mt][nt][2] * w0 + cfr[mt][nt][3] * w1;
            }
        }
#pragma unroll
        for (int mt = 0; mt < 2; mt++)
#pragma unroll
            for (int nh = 0; nh < NH; nh++) {
#pragma unroll
                for (int off = 1; off < 4; off <<= 1) {
                    pl[mt][nh] += __shfl_xor_sync(0xffffffffu, pl[mt][nh], off, 4);
                    ph[mt][nh] += __shfl_xor_sync(0xffffffffu, ph[mt][nh], off, 4);
                }
                if (tig == 0) {
                    int h = (n0 + wn * 32) / CC + nh;
                    int m_lo = m0 + wm * 32 + mt * 16 + g;
                    int m_hi = m_lo + 8;
                    if (m_lo < M)
                        *(float2*)(es + m_lo * 8 + h * 2) =
                            make_float2(__expf(pl[mt][nh]), __expf(0.2f * pl[mt][nh]));
                    if (m_hi < M)
                        *(float2*)(es + m_hi * 8 + h * 2) =
                            make_float2(__expf(ph[mt][nh]), __expf(0.2f * ph[mt][nh]));
                }
            }
    }

#pragma unroll
    for (int mt = 0; mt < 2; mt++) {
        int m_lo = m0 + wm * 32 + mt * 16 + g;
        int m_hi = m_lo + 8;
#pragma unroll
        for (int nt = 0; nt < 4; nt++) {
            int col = n0 + wn * 32 + nt * 8 + 2 * tig;
            if (m_lo < M)
                *(__half2*)(C + (size_t)m_lo * N + col) =
                    __floats2half2_rn(cfr[mt][nt][0], cfr[mt][nt][1]);
            if (m_hi < M)
                *(__half2*)(C + (size_t)m_hi * N + col) =
                    __floats2half2_rn(cfr[mt][nt][2], cfr[mt][nt][3]);
        }
    }
}

// -------- pipelined edge accumulation (double-buffered batches of 4) -----------
template <int D> struct EB {
    int cnt;
    float2 v[4];
    uint2 u[4];
};
template <int D>
__device__ __forceinline__ void eload(EB<D>& b, const int* __restrict__ srt,
                                      const float* __restrict__ es,
                                      const __half* __restrict__ hs,
                                      int i, int end, int lane, int h) {
    int cnt = end - i;
    b.cnt = cnt > 4 ? 4 : cnt;
#pragma unroll
    for (int j = 0; j < 4; j++) {
        int idx = i + ((j < b.cnt) ? j : 0);
        int s = __ldg(&srt[idx]);
        b.v[j] = __ldg((const float2*)(es + s * 8 + h * 2));
        if (D == 128)
            b.u[j] = *(const uint2*)(hs + (size_t)s * 128 + lane * 4);
        else
            b.u[j].x = *(const unsigned*)(hs + (size_t)s * 64 + lane * 2);
    }
}
template <int D>
__device__ __forceinline__ void eproc(const EB<D>& b, float E1, float E2,
                                      float& den, float* a) {
#pragma unroll
    for (int j = 0; j < 4; j++) {
        float ee = (j < b.cnt) ? fmaxf(b.v[j].x * E1, b.v[j].y * E2) : 0.f;
        den += ee;
        if (D == 128) {
            union { uint2 uu; __half2 h2[2]; } cv; cv.uu = b.u[j];
            float2 p0 = __half22float2(cv.h2[0]);
            float2 p1 = __half22float2(cv.h2[1]);
            a[0] += ee * p0.x; a[1] += ee * p0.y;
            a[2] += ee * p1.x; a[3] += ee * p1.y;
        } else {
            union { unsigned uu; __half2 h2; } cv; cv.uu = b.u[j].x;
            float2 p = __half22float2(cv.h2);
            a[0] += ee * p.x; a[1] += ee * p.y;
        }
    }
}
template <int D>
__device__ __forceinline__ void edge_accum(
        const int* __restrict__ off, const int* __restrict__ srt,
        const float* __restrict__ es, const float* __restrict__ ed,
        const __half* __restrict__ hs,
        int d, int lane, int h, float& den, float* a) {
    int start = __ldg(&off[d]), end = __ldg(&off[d + 1]);
    if (start >= end) return;
    float2 edv = __ldg((const float2*)(ed + d * 8 + h * 2));
    float E1 = edv.x, E2 = edv.y;
    EB<D> b0, b1;
    eload<D>(b0, srt, es, hs, start, end, lane, h);
    int i = start + 4;
    while (i < end) {
        eload<D>(b1, srt, es, hs, i, end, lane, h);
        eproc<D>(b0, E1, E2, den, a);
        i += 4;
        if (i >= end) { eproc<D>(b1, E1, E2, den, a); return; }
        eload<D>(b0, srt, es, hs, i, end, lane, h);
        eproc<D>(b1, E1, E2, den, a);
        i += 4;
    }
    eproc<D>(b0, E1, E2, den, a);
}

// -------- paper-dst gather (pp + ap) ------------------------------------------
template <int D>
__global__ void __launch_bounds__(256)
gat_gatherP(const int* __restrict__ off0, const int* __restrict__ srt0,
            const float* __restrict__ es0, const float* __restrict__ ed0,
            const __half* __restrict__ hs0,
            const int* __restrict__ off1, const int* __restrict__ srt1,
            const float* __restrict__ es1, const float* __restrict__ ed1,
            const __half* __restrict__ hs1,
            float* __restrict__ accP,
            const float* __restrict__ bP0, const float* __restrict__ bP1, int relu) {
    constexpr int CPL = D / 32;
    int warp = (blockIdx.x * blockDim.x + threadIdx.x) >> 5;
    int lane = threadIdx.x & 31;
    if (warp >= NP) return;
    int h = lane >> 3;
    int cb = lane * CPL;
    float denA = 0.f, denB = 0.f;
    float aA[4] = {0.f, 0.f, 0.f, 0.f}, aB[4] = {0.f, 0.f, 0.f, 0.f};
    edge_accum<D>(off0, srt0, es0, ed0, hs0, warp, lane, h, denA, aA);
    edge_accum<D>(off1, srt1, es1, ed1, hs1, warp, lane, h, denB, aB);
    float invA = 1.f / (denA + 1e-16f);
    float invB = 1.f / (denB + 1e-16f);
    float* dp = accP + (size_t)warp * D + cb;
    if (D == 128) {
        float4 b0 = *(const float4*)(bP0 + cb);
        float4 b1 = *(const float4*)(bP1 + cb);
        float4 o = make_float4(aA[0] * invA + aB[0] * invB + b0.x + b1.x,
                               aA[1] * invA + aB[1] * invB + b0.y + b1.y,
                               aA[2] * invA + aB[2] * invB + b0.z + b1.z,
                               aA[3] * invA + aB[3] * invB + b0.w + b1.w);
        if (relu) {
            o.x = fmaxf(o.x, 0.f); o.y = fmaxf(o.y, 0.f);
            o.z = fmaxf(o.z, 0.f); o.w = fmaxf(o.w, 0.f);
        }
        *(float4*)dp = o;
    } else {
        float2 b0 = *(const float2*)(bP0 + cb);
        float2 b1 = *(const float2*)(bP1 + cb);
        float2 o = make_float2(aA[0] * invA + aB[0] * invB + b0.x + b1.x,
                               aA[1] * invA + aB[1] * invB + b0.y + b1.y);
        if (relu) { o.x = fmaxf(o.x, 0.f); o.y = fmaxf(o.y, 0.f); }
        *(float2*)dp = o;
    }
}

// -------- author-dst gather (pa) ----------------------------------------------
template <int D>
__global__ void __launch_bounds__(256)
gat_gatherA(const int* __restrict__ off2, const int* __restrict__ srt2,
            const float* __restrict__ es2, const float* __restrict__ ed2,
            const __half* __restrict__ hs2,
            float* __restrict__ accA, const float* __restrict__ bA0, int relu) {
    constexpr int CPL = D / 32;
    int warp = (blockIdx.x * blockDim.x + threadIdx.x) >> 5;
    int lane = threadIdx.x & 31;
    if (warp >= NA) return;
    int h = lane >> 3;
    int cb = lane * CPL;
    float den = 0.f;
    float a[4] = {0.f, 0.f, 0.f, 0.f};
    edge_accum<D>(off2, srt2, es2, ed2, hs2, warp, lane, h, den, a);
    float inv = 1.f / (den + 1e-16f);
    float* dp = accA + (size_t)warp * D + cb;
    if (D == 128) {
        float4 b0 = *(const float4*)(bA0 + cb);
        float4 o = make_float4(a[0] * inv + b0.x, a[1] * inv + b0.y,
                               a[2] * inv + b0.z, a[3] * inv + b0.w);
        if (relu) {
            o.x = fmaxf(o.x, 0.f); o.y = fmaxf(o.y, 0.f);
            o.z = fmaxf(o.z, 0.f); o.w = fmaxf(o.w, 0.f);
        }
        *(float4*)dp = o;
    } else {
        float2 b0 = *(const float2*)(bA0 + cb);
        float2 o = make_float2(a[0] * inv + b0.x, a[1] * inv + b0.y);
        if (relu) { o.x = fmaxf(o.x, 0.f); o.y = fmaxf(o.y, 0.f); }
        *(float2*)dp = o;
    }
}

// -------- combined gather over all dst nodes (layer 2) -------------------------
template <int D>
__global__ void __launch_bounds__(256)
gat_gather_all(const int* __restrict__ off0, const int* __restrict__ srt0,
               const float* __restrict__ es0, const float* __restrict__ ed0,
               const __half* __restrict__ hs0,
               const int* __restrict__ off1, const int* __restrict__ srt1,
               const float* __restrict__ es1, const float* __restrict__ ed1,
               const __half* __restrict__ hs1,
               const int* __restrict__ off2, const int* __restrict__ srt2,
               const float* __restrict__ es2, const float* __restrict__ ed2,
               const __half* __restrict__ hs2,
               float* __restrict__ accP, float* __restrict__ accA,
               const float* __restrict__ bP0, const float* __restrict__ bP1,
               const float* __restrict__ bA0, int relu) {
    constexpr int CPL = D / 32;
    int warp = (blockIdx.x * blockDim.x + threadIdx.x) >> 5;
    int lane = threadIdx.x & 31;
    int h = lane >> 3;
    int cb = lane * CPL;
    if (warp < NP) {
        int d = warp;
        float denA = 0.f, denB = 0.f;
        float aA[4] = {0.f, 0.f, 0.f, 0.f}, aB[4] = {0.f, 0.f, 0.f, 0.f};
        edge_accum<D>(off0, srt0, es0, ed0, hs0, d, lane, h, denA, aA);
        edge_accum<D>(off1, srt1, es1, ed1, hs1, d, lane, h, denB, aB);
        float invA = 1.f / (denA + 1e-16f);
        float invB = 1.f / (denB + 1e-16f);
        float* dp = accP + (size_t)d * D + cb;
        if (D == 128) {
            float4 b0 = *(const float4*)(bP0 + cb);
            float4 b1 = *(const float4*)(bP1 + cb);
            float4 o = make_float4(aA[0] * invA + aB[0] * invB + b0.x + b1.x,
                                   aA[1] * invA + aB[1] * invB + b0.y + b1.y,
                                   aA[2] * invA + aB[2] * invB + b0.z + b1.z,
                                   aA[3] * invA + aB[3] * invB + b0.w + b1.w);
            if (relu) {
                o.x = fmaxf(o.x, 0.f); o.y = fmaxf(o.y, 0.f);
                o.z = fmaxf(o.z, 0.f); o.w = fmaxf(o.w, 0.f);
            }
            *(float4*)dp = o;
        } else {
            float2 b0 = *(const float2*)(bP0 + cb);
            float2 b1 = *(const float2*)(bP1 + cb);
            float2 o = make_float2(aA[0] * invA + aB[0] * invB + b0.x + b1.x,
                                   aA[1] * invA + aB[1] * invB + b0.y + b1.y);
            if (relu) { o.x = fmaxf(o.x, 0.f); o.y = fmaxf(o.y, 0.f); }
            *(float2*)dp = o;
        }
    } else if (warp < NP + NA) {
        int d = warp - NP;
        float den = 0.f;
        float a[4] = {0.f, 0.f, 0.f, 0.f};
        edge_accum<D>(off2, srt2, es2, ed2, hs2, d, lane, h, den, a);
        float inv = 1.f / (den + 1e-16f);
        float* dp = accA + (size_t)d * D + cb;
        if (D == 128) {
            float4 b0 = *(const float4*)(bA0 + cb);
            float4 o = make_float4(a[0] * inv + b0.x, a[1] * inv + b0.y,
                                   a[2] * inv + b0.z, a[3] * inv + b0.w);
            if (relu) {
                o.x = fmaxf(o.x, 0.f); o.y = fmaxf(o.y, 0.f);
                o.z = fmaxf(o.z, 0.f); o.w = fmaxf(o.w, 0.f);
            }
            *(float4*)dp = o;
        } else {
            float2 b0 = *(const float2*)(bA0 + cb);
            float2 o = make_float2(a[0] * inv + b0.x, a[1] * inv + b0.y);
            if (relu) { o.x = fmaxf(o.x, 0.f); o.y = fmaxf(o.y, 0.f); }
            *(float2*)dp = o;
        }
    }
}

// =============================================================================
extern "C" void kernel_launch(void* const* d_in, const int* in_sizes, int n_in,
                              void* d_out, int out_size) {
    const float* x_p = (const float*)d_in[0];
    const float* x_a = (const float*)d_in[1];
    const int* src_pp = (const int*)d_in[2];
    const int* dst_pp = (const int*)d_in[3];
    const int* src_ap = (const int*)d_in[4];
    const int* dst_ap = (const int*)d_in[5];
    const int* src_pa = (const int*)d_in[6];
    const int* dst_pa = (const int*)d_in[7];
    const float* Wsrc1 = (const float*)d_in[8];
    const float* Wdst1 = (const float*)d_in[9];
    const float* asrc1 = (const float*)d_in[10];
    const float* adst1 = (const float*)d_in[11];
    const float* b1 = (const float*)d_in[12];
    const float* Wsrc2 = (const float*)d_in[13];
    const float* Wdst2 = (const float*)d_in[14];
    const float* asrc2 = (const float*)d_in[15];
    const float* adst2 = (const float*)d_in[16];
    const float* b2 = (const float*)d_in[17];
    float* out = (float*)d_out;

    void* p;
    cudaGetSymbolAddress(&p, g_hs0);    __half* hs0 = (__half*)p;
    cudaGetSymbolAddress(&p, g_hs1);    __half* hs1 = (__half*)p;
    cudaGetSymbolAddress(&p, g_hs2);    __half* hs2 = (__half*)p;
    cudaGetSymbolAddress(&p, g_hs0b);   __half* hs0b = (__half*)p;
    cudaGetSymbolAddress(&p, g_hs1b);   __half* hs1b = (__half*)p;
    cudaGetSymbolAddress(&p, g_hs2b);   __half* hs2b = (__half*)p;
    cudaGetSymbolAddress(&p, g_es);     float* es   = (float*)p;
    cudaGetSymbolAddress(&p, g_ed);     float* ed   = (float*)p;
    cudaGetSymbolAddress(&p, g_esb);    float* esb  = (float*)p;
    cudaGetSymbolAddress(&p, g_edb);    float* edb  = (float*)p;
    cudaGetSymbolAddress(&p, g_accp);   float* accp = (float*)p;
    cudaGetSymbolAddress(&p, g_acca);   float* acca = (float*)p;
    cudaGetSymbolAddress(&p, g_vd1);    float* vd1  = (float*)p;
    cudaGetSymbolAddress(&p, g_vd2);    float* vd2  = (float*)p;
    cudaGetSymbolAddress(&p, g_off_pp); int* off_pp = (int*)p;
    cudaGetSymbolAddress(&p, g_off_ap); int* off_ap = (int*)p;
    cudaGetSymbolAddress(&p, g_off_pa); int* off_pa = (int*)p;
    cudaGetSymbolAddress(&p, g_srt);    int* srt    = (int*)p;
    cudaGetSymbolAddress(&p, g_writer); int* writer = (int*)p;

    int* srt_pp = srt;
    int* srt_ap = srt + EPP;
    int* srt_pa = srt + EPP + EAP;

    float* es0 = es, *es1 = es + NP * 8, *es2 = es + 2 * NP * 8;
    float* ed0 = ed, *ed1 = ed + NP * 8, *ed2 = ed + 2 * NP * 8;
    float* es0b = esb, *es1b = esb + NP * 8, *es2b = esb + 2 * NP * 8;
    float* ed0b = edb, *ed1b = edb + NP * 8, *ed2b = edb + 2 * NP * 8;

    const int TB = 256;
    auto blocks = [](long long n) { return (int)((n + 255) / 256); };

    cudaStream_t s2;
    cudaStreamCreateWithFlags(&s2, cudaStreamNonBlocking);
    cudaEvent_t eFork, eMMA2, eCSR, eS2;
    cudaEventCreateWithFlags(&eFork, cudaEventDisableTiming);
    cudaEventCreateWithFlags(&eMMA2, cudaEventDisableTiming);
    cudaEventCreateWithFlags(&eCSR, cudaEventDisableTiming);
    cudaEventCreateWithFlags(&eS2, cudaEventDisableTiming);

    cudaEventRecord(eFork, 0);
    cudaStreamWaitEvent(s2, eFork, 0);

    // ---- s2: CSR chain, then independent mma3_L1, then author-side path ----
    cudaMemsetAsync(off_pp, 0, (NP + 1) * sizeof(int), s2);
    cudaMemsetAsync(off_ap, 0, (NP + 1) * sizeof(int), s2);
    cudaMemsetAsync(off_pa, 0, (NA + 1) * sizeof(int), s2);
    count3<<<blocks(EPP + EAP + EPA), TB, 0, s2>>>(dst_pp, dst_ap, dst_pa,
                                                   off_pp, off_ap, off_pa);
    scan3<<<3, 1024, 0, s2>>>(off_pp, off_ap, off_pa, writer);
    scatter3<<<blocks(EPP + EAP + EPA), TB, 0, s2>>>(src_pp, dst_pp, src_ap, dst_ap,
                                                     src_pa, dst_pa, writer, srt);
    cudaEventRecord(eCSR, s2);
    {   // mma3_L1: x_p rel2 -> hs2, es2 (independent of vd, CSR result order ok)
        dim3 gP(2, (NP + 127) / 128);
        mma_es<32, 0><<<gP, 256, 0, s2>>>(x_p, Wsrc1 + 2 * 128 * 128, hs2, es2,
                                          asrc1 + 2 * 128, nullptr, nullptr,
                                          nullptr, nullptr, NP, 128);
    }
    cudaStreamWaitEvent(s2, eMMA2, 0);   // needs ed2 (from mma2 on stream 0)
    gat_gatherA<128><<<blocks((long long)NA * 32), TB, 0, s2>>>(
        off_pa, srt_pa, es2, ed2, hs2, acca, b1 + 256, 1);
    {   // layer-2 ap GEMM: acca -> hs1b/es1b, ed2b (vd2 rel2)
        dim3 gA(1, (NA + 127) / 128);
        mma_es<16, 1><<<gA, 256, 0, s2>>>(acca, Wsrc2 + 1 * 128 * 64, hs1b, es1b,
                                          asrc2 + 1 * 64, vd2 + 2 * 512, nullptr,
                                          ed2b, nullptr, NA, 64);
    }
    cudaEventRecord(eS2, s2);

    // ---- stream 0: paper-side critical path ----
    compute_vd<<<blocks(2 * 3 * 128 * 4), TB>>>(Wdst1, adst1, Wdst2, adst2, vd1, vd2);
    {
        dim3 gP(2, (NP + 127) / 128), gA(2, (NA + 127) / 128);
        mma_es<32, 2><<<gP, 256>>>(x_p, Wsrc1 + 0 * 128 * 128, hs0, es0, asrc1 + 0 * 128,
                                   vd1 + 0 * 512, vd1 + 1 * 512, ed0, ed1, NP, 128);
        mma_es<32, 1><<<gA, 256>>>(x_a, Wsrc1 + 1 * 128 * 128, hs1, es1, asrc1 + 1 * 128,
                                   vd1 + 2 * 512, nullptr, ed2, nullptr, NA, 128);
    }
    cudaEventRecord(eMMA2, 0);
    cudaStreamWaitEvent(0, eCSR, 0);
    gat_gatherP<128><<<blocks((long long)NP * 32), TB>>>(
        off_pp, srt_pp, es0, ed0, hs0,
        off_ap, srt_ap, es1, ed1, hs1,
        accp, b1 + 0, b1 + 128, 1);
    {
        dim3 gP(1, (NP + 127) / 128);
        mma_es<16, 2><<<gP, 256>>>(accp, Wsrc2 + 0 * 128 * 64, hs0b, es0b, asrc2 + 0 * 64,
                                   vd2 + 0 * 512, vd2 + 1 * 512, ed0b, ed1b, NP, 64);
        mma_es<16, 0><<<gP, 256>>>(accp, Wsrc2 + 2 * 128 * 64, hs2b, es2b, asrc2 + 2 * 64,
                                   nullptr, nullptr, nullptr, nullptr, NP, 64);
    }
    cudaStreamWaitEvent(0, eS2, 0);
    gat_gather_all<64><<<blocks((long long)(NP + NA) * 32), TB>>>(
        off_pp, srt_pp, es0b, ed0b, hs0b,
        off_ap, srt_ap, es1b, ed1b, hs1b,
        off_pa, srt_pa, es2b, ed2b, hs2b,
        out, out + (size_t)NP * 64, b2 + 0, b2 + 64, b2 + 128, 0);
}

// round 16
// speedup vs baseline: 1.0392x; 1.0392x over previous
#include <cuda_runtime.h>
#include <cuda_bf16.h>
#include <cuda_fp16.h>
#include <cstdint>

#define NP 100000
#define NA 50000
#define EPP 1600000
#define EAP 800000
#define EPA 800000

// ---------------- scratch ----------------------------------------------------
__device__ __align__(16) __half g_hs0[NP * 128];
__device__ __align__(16) __half g_hs1[NA * 128];
__device__ __align__(16) __half g_hs2[NP * 128];
__device__ __align__(16) __half g_hs0b[NP * 64];
__device__ __align__(16) __half g_hs1b[NA * 64];
__device__ __align__(16) __half g_hs2b[NP * 64];
__device__ __align__(16) float g_es[3 * NP * 8];
__device__ __align__(16) float g_ed[3 * NP * 8];
__device__ __align__(16) float g_esb[3 * NP * 8];
__device__ __align__(16) float g_edb[3 * NP * 8];
__device__ __align__(16) float g_accp[NP * 128];
__device__ __align__(16) float g_acca[NA * 128];
__device__ __align__(16) float g_vd1[3 * 512];
__device__ __align__(16) float g_vd2[3 * 512];
// CSR scratch
__device__ int g_off_pp[NP + 1];
__device__ int g_off_ap[NP + 1];
__device__ int g_off_pa[NA + 1];
__device__ int g_srt[EPP + EAP + EPA];
__device__ int g_writer[NP + NP + NA];

// ---------------- helpers ----------------------------------------------------
__device__ __forceinline__ uint32_t tf32(float x) {
    uint32_t r;
    asm("cvt.rna.tf32.f32 %0, %1;" : "=r"(r) : "f"(x));
    return r;
}
__device__ __forceinline__ void mma_tf32(float* d, const uint32_t* a, const uint32_t* b) {
    asm("mma.sync.aligned.m16n8k8.row.col.f32.tf32.tf32.f32 "
        "{%0,%1,%2,%3},{%4,%5,%6,%7},{%8,%9},{%0,%1,%2,%3};"
        : "+f"(d[0]), "+f"(d[1]), "+f"(d[2]), "+f"(d[3])
        : "r"(a[0]), "r"(a[1]), "r"(a[2]), "r"(a[3]), "r"(b[0]), "r"(b[1]));
}

// ---------------- batched CSR build -------------------------------------------
__global__ void count3(const int* __restrict__ d0, const int* __restrict__ d1,
                       const int* __restrict__ d2, int* __restrict__ o0,
                       int* __restrict__ o1, int* __restrict__ o2) {
    int i = blockIdx.x * blockDim.x + threadIdx.x;
    if (i < EPP) atomicAdd(&o0[d0[i] + 1], 1);
    else if (i < EPP + EAP) atomicAdd(&o1[d1[i - EPP] + 1], 1);
    else if (i < EPP + EAP + EPA) atomicAdd(&o2[d2[i - EPP - EAP] + 1], 1);
}
__device__ void scan_one(int* __restrict__ off, int* __restrict__ writer, int n, int nw) {
    __shared__ int ssum[1024];
    int tid = threadIdx.x;
    int running = 0;
    for (int base = 0; base < n; base += 4096) {
        int idx = base + tid * 4;
        int v0 = idx + 0 < n ? off[idx + 0] : 0;
        int v1 = idx + 1 < n ? off[idx + 1] : 0;
        int v2 = idx + 2 < n ? off[idx + 2] : 0;
        int v3 = idx + 3 < n ? off[idx + 3] : 0;
        int p0 = v0, p1 = p0 + v1, p2 = p1 + v2, p3 = p2 + v3;
        ssum[tid] = p3;
        __syncthreads();
        for (int o = 1; o < 1024; o <<= 1) {
            int val = 0;
            if (tid >= o) val = ssum[tid - o];
            __syncthreads();
            if (tid >= o) ssum[tid] += val;
            __syncthreads();
        }
        int excl = running + (tid ? ssum[tid - 1] : 0);
        int total = ssum[1023];
        __syncthreads();
        int s0 = excl + p0, s1 = excl + p1, s2 = excl + p2, s3 = excl + p3;
        if (idx + 0 < n) { off[idx + 0] = s0; if (idx + 0 < nw) writer[idx + 0] = s0; }
        if (idx + 1 < n) { off[idx + 1] = s1; if (idx + 1 < nw) writer[idx + 1] = s1; }
        if (idx + 2 < n) { off[idx + 2] = s2; if (idx + 2 < nw) writer[idx + 2] = s2; }
        if (idx + 3 < n) { off[idx + 3] = s3; if (idx + 3 < nw) writer[idx + 3] = s3; }
        running += total;
    }
}
__global__ void __launch_bounds__(1024)
scan3(int* __restrict__ o0, int* __restrict__ o1, int* __restrict__ o2,
      int* __restrict__ writer) {
    if (blockIdx.x == 0)      scan_one(o0, writer, NP + 1, NP);
    else if (blockIdx.x == 1) scan_one(o1, writer + NP, NP + 1, NP);
    else                      scan_one(o2, writer + 2 * NP, NA + 1, NA);
}
__global__ void scatter3(const int* __restrict__ s0, const int* __restrict__ d0,
                         const int* __restrict__ s1, const int* __restrict__ d1,
                         const int* __restrict__ s2, const int* __restrict__ d2,
                         int* __restrict__ writer, int* __restrict__ srt) {
    int i = blockIdx.x * blockDim.x + threadIdx.x;
    if (i < EPP) {
        int pos = atomicAdd(&writer[d0[i]], 1);
        srt[pos] = s0[i];
    } else if (i < EPP + EAP) {
        int e = i - EPP;
        int pos = atomicAdd(&writer[NP + d1[e]], 1);
        srt[EPP + pos] = s1[e];
    } else if (i < EPP + EAP + EPA) {
        int e = i - EPP - EAP;
        int pos = atomicAdd(&writer[2 * NP + d2[e]], 1);
        srt[EPP + EAP + pos] = s2[e];
    }
}

// ---------------- vd folding ---------------------------------------------------
__global__ void compute_vd(const float* __restrict__ Wd1, const float* __restrict__ ad1,
                           const float* __restrict__ Wd2, const float* __restrict__ ad2,
                           float* __restrict__ vd1, float* __restrict__ vd2) {
    int i = blockIdx.x * blockDim.x + threadIdx.x;
    if (i >= 2 * 3 * 128 * 4) return;
    int layer = i >= 3 * 128 * 4;
    int ii = i - layer * 3 * 128 * 4;
    int h = ii & 3;
    int f = (ii >> 2) & 127;
    int r = ii >> 9;
    int D = layer ? 64 : 128;
    int C = D / 4;
    const float* W = (layer ? Wd2 : Wd1) + (size_t)r * 128 * D + (size_t)f * D + h * C;
    const float* a = (layer ? ad2 : ad1) + r * 4 * C + h * C;
    float s = 0.f;
    for (int c = 0; c < C; c++) s += W[c] * a[c];
    (layer ? vd2 : vd1)[r * 512 + f * 4 + h] = s;
}

// ============== tf32 MMA GEMM, SINGLE B (author relations), fused ed ==========
template <int CC, int NED>
__global__ void __launch_bounds__(256)
mma_es(const float* __restrict__ A, const float* __restrict__ B,
       __half* __restrict__ C, float* __restrict__ es,
       const float* __restrict__ a_s,
       const float* __restrict__ vdA, const float* __restrict__ vdB,
       float* __restrict__ edA, float* __restrict__ edB,
       int M, int N) {
    const int K = 128;
    const int BKc = 16;
    __shared__ __align__(16) float As[2][128][BKc + 4];
    __shared__ __align__(16) float Bs[2][BKc][64 + 8];
    __shared__ __align__(16) float vds[128][8];
    int tid = threadIdx.x;
    int lane = tid & 31, wid = tid >> 5;
    int wm = wid & 3, wn = wid >> 2;
    int g = lane >> 2, tig = lane & 3;
    int m0 = blockIdx.y * 128, n0 = blockIdx.x * 64;

    if (NED > 0) {
        for (int i = tid; i < 1024; i += 256) {
            int k = i >> 3, j = i & 7;
            float v = 0.f;
            if (j < 4) v = vdA[k * 4 + j];
            else if (NED == 2) v = vdB[k * 4 + (j - 4)];
            vds[k][j] = v;
        }
    }

    float cfr[2][4][4];
#pragma unroll
    for (int mt = 0; mt < 2; mt++)
#pragma unroll
        for (int nt = 0; nt < 4; nt++)
#pragma unroll
            for (int q = 0; q < 4; q++) cfr[mt][nt][q] = 0.f;
    float edf[2][4];
#pragma unroll
    for (int mt = 0; mt < 2; mt++)
#pragma unroll
        for (int q = 0; q < 4; q++) edf[mt][q] = 0.f;
    bool do_ed = (NED > 0) && (wn == 0) && (blockIdx.x == 0);

    int aRow = tid >> 1, aK = (tid & 1) * 8;
    int bRow = tid >> 4, bC = (tid & 15) * 4;

    float4 ra0, ra1, rb;
    auto loadg = [&](int k0) {
        int m = m0 + aRow;
        if (m < M) {
            ra0 = *(const float4*)(A + (size_t)m * K + k0 + aK);
            ra1 = *(const float4*)(A + (size_t)m * K + k0 + aK + 4);
        } else {
            ra0 = make_float4(0.f, 0.f, 0.f, 0.f);
            ra1 = ra0;
        }
        rb = *(const float4*)(B + (size_t)(k0 + bRow) * N + n0 + bC);
    };
    auto stores = [&](int buf) {
        *(float4*)&As[buf][aRow][aK] = ra0;
        *(float4*)&As[buf][aRow][aK + 4] = ra1;
        *(float4*)&Bs[buf][bRow][bC] = rb;
    };

    loadg(0);
    stores(0);
    __syncthreads();

#pragma unroll 1
    for (int c = 0; c < 8; c++) {
        if (c + 1 < 8) loadg((c + 1) * BKc);
        int buf = c & 1;
#pragma unroll
        for (int kk = 0; kk < BKc; kk += 8) {
            uint32_t af[2][4], bf[4][2];
#pragma unroll
            for (int mt = 0; mt < 2; mt++) {
                int rm = wm * 32 + mt * 16;
                af[mt][0] = tf32(As[buf][rm + g][kk + tig]);
                af[mt][1] = tf32(As[buf][rm + g + 8][kk + tig]);
                af[mt][2] = tf32(As[buf][rm + g][kk + tig + 4]);
                af[mt][3] = tf32(As[buf][rm + g + 8][kk + tig + 4]);
            }
#pragma unroll
            for (int nt = 0; nt < 4; nt++) {
                int cn = wn * 32 + nt * 8;
                bf[nt][0] = tf32(Bs[buf][kk + tig][cn + g]);
                bf[nt][1] = tf32(Bs[buf][kk + tig + 4][cn + g]);
            }
#pragma unroll
            for (int mt = 0; mt < 2; mt++)
#pragma unroll
                for (int nt = 0; nt < 4; nt++)
                    mma_tf32(cfr[mt][nt], af[mt], bf[nt]);
            if (do_ed) {
                uint32_t bvd[2];
                int kg = c * BKc + kk;
                bvd[0] = tf32(vds[kg + tig][g]);
                bvd[1] = tf32(vds[kg + tig + 4][g]);
                mma_tf32(edf[0], af[0], bvd);
                mma_tf32(edf[1], af[1], bvd);
            }
        }
        if (c + 1 < 8) stores((c + 1) & 1);
        __syncthreads();
    }

    if (do_ed) {
        auto edst = [&](int m, int col, float v) {
            int rel = col >> 2;
            if (rel == 1 && NED < 2) return;
            int h = col & 3;
            float* dst = rel ? edB : edA;
            if (m < M)
                *(float2*)(dst + m * 8 + h * 2) =
                    make_float2(__expf(v), __expf(0.2f * v));
        };
#pragma unroll
        for (int mt = 0; mt < 2; mt++) {
            int m_lo = m0 + wm * 32 + mt * 16 + g;
            int m_hi = m_lo + 8;
            edst(m_lo, 2 * tig + 0, edf[mt][0]);
            edst(m_lo, 2 * tig + 1, edf[mt][1]);
            edst(m_hi, 2 * tig + 0, edf[mt][2]);
            edst(m_hi, 2 * tig + 1, edf[mt][3]);
        }
    }

    {
        constexpr int NH = 32 / CC;
        float pl[2][NH], ph[2][NH];
#pragma unroll
        for (int mt = 0; mt < 2; mt++)
#pragma unroll
            for (int nh = 0; nh < NH; nh++) { pl[mt][nh] = 0.f; ph[mt][nh] = 0.f; }
#pragma unroll
        for (int nt = 0; nt < 4; nt++) {
            int nh = (nt * 8) / CC;
            float w0 = __ldg(&a_s[n0 + wn * 32 + nt * 8 + 2 * tig]);
            float w1 = __ldg(&a_s[n0 + wn * 32 + nt * 8 + 2 * tig + 1]);
#pragma unroll
            for (int mt = 0; mt < 2; mt++) {
                pl[mt][nh] += cfr[mt][nt][0] * w0 + cfr[mt][nt][1] * w1;
                ph[mt][nh] += cfr[mt][nt][2] * w0 + cfr[mt][nt][3] * w1;
            }
        }
#pragma unroll
        for (int mt = 0; mt < 2; mt++)
#pragma unroll
            for (int nh = 0; nh < NH; nh++) {
#pragma unroll
                for (int off = 1; off < 4; off <<= 1) {
                    pl[mt][nh] += __shfl_xor_sync(0xffffffffu, pl[mt][nh], off, 4);
                    ph[mt][nh] += __shfl_xor_sync(0xffffffffu, ph[mt][nh], off, 4);
                }
                if (tig == 0) {
                    int h = (n0 + wn * 32) / CC + nh;
                    int m_lo = m0 + wm * 32 + mt * 16 + g;
                    int m_hi = m_lo + 8;
                    if (m_lo < M)
                        *(float2*)(es + m_lo * 8 + h * 2) =
                            make_float2(__expf(pl[mt][nh]), __expf(0.2f * pl[mt][nh]));
                    if (m_hi < M)
                        *(float2*)(es + m_hi * 8 + h * 2) =
                            make_float2(__expf(ph[mt][nh]), __expf(0.2f * ph[mt][nh]));
                }
            }
    }

#pragma unroll
    for (int mt = 0; mt < 2; mt++) {
        int m_lo = m0 + wm * 32 + mt * 16 + g;
        int m_hi = m_lo + 8;
#pragma unroll
        for (int nt = 0; nt < 4; nt++) {
            int col = n0 + wn * 32 + nt * 8 + 2 * tig;
            if (m_lo < M)
                *(__half2*)(C + (size_t)m_lo * N + col) =
                    __floats2half2_rn(cfr[mt][nt][0], cfr[mt][nt][1]);
            if (m_hi < M)
                *(__half2*)(C + (size_t)m_hi * N + col) =
                    __floats2half2_rn(cfr[mt][nt][2], cfr[mt][nt][3]);
        }
    }
}

// ============== DUAL-B tf32 MMA GEMM (paper relations, shared A) ==============
template <int CC>
__global__ void __launch_bounds__(256)
mma_es2(const float* __restrict__ A,
        const float* __restrict__ B0, const float* __restrict__ B1,
        __half* __restrict__ C0, __half* __restrict__ C1,
        float* __restrict__ esA, float* __restrict__ esB,
        const float* __restrict__ a_s0, const float* __restrict__ a_s1,
        const float* __restrict__ vdA, const float* __restrict__ vdB,
        float* __restrict__ edA, float* __restrict__ edB,
        int M, int N) {
    const int K = 128;
    const int BKc = 16;
    __shared__ __align__(16) float As[2][128][BKc + 4];
    __shared__ __align__(16) float Bs0[2][BKc][64 + 8];
    __shared__ __align__(16) float Bs1[2][BKc][64 + 8];
    __shared__ __align__(16) float vds[128][8];
    int tid = threadIdx.x;
    int lane = tid & 31, wid = tid >> 5;
    int wm = wid & 3, wn = wid >> 2;
    int g = lane >> 2, tig = lane & 3;
    int m0 = blockIdx.y * 128, n0 = blockIdx.x * 64;

    for (int i = tid; i < 1024; i += 256) {
        int k = i >> 3, j = i & 7;
        vds[k][j] = (j < 4) ? vdA[k * 4 + j] : vdB[k * 4 + (j - 4)];
    }

    float cfr0[2][4][4], cfr1[2][4][4];
#pragma unroll
    for (int mt = 0; mt < 2; mt++)
#pragma unroll
        for (int nt = 0; nt < 4; nt++)
#pragma unroll
            for (int q = 0; q < 4; q++) { cfr0[mt][nt][q] = 0.f; cfr1[mt][nt][q] = 0.f; }
    float edf[2][4];
#pragma unroll
    for (int mt = 0; mt < 2; mt++)
#pragma unroll
        for (int q = 0; q < 4; q++) edf[mt][q] = 0.f;
    bool do_ed = (wn == 0) && (blockIdx.x == 0);

    int aRow = tid >> 1, aK = (tid & 1) * 8;
    int bRow = tid >> 4, bC = (tid & 15) * 4;

    float4 ra0, ra1, rb0, rb1;
    auto loadg = [&](int k0) {
        int m = m0 + aRow;
        if (m < M) {
            ra0 = *(const float4*)(A + (size_t)m * K + k0 + aK);
            ra1 = *(const float4*)(A + (size_t)m * K + k0 + aK + 4);
        } else {
            ra0 = make_float4(0.f, 0.f, 0.f, 0.f);
            ra1 = ra0;
        }
        rb0 = *(const float4*)(B0 + (size_t)(k0 + bRow) * N + n0 + bC);
        rb1 = *(const float4*)(B1 + (size_t)(k0 + bRow) * N + n0 + bC);
    };
    auto stores = [&](int buf) {
        *(float4*)&As[buf][aRow][aK] = ra0;
        *(float4*)&As[buf][aRow][aK + 4] = ra1;
        *(float4*)&Bs0[buf][bRow][bC] = rb0;
        *(float4*)&Bs1[buf][bRow][bC] = rb1;
    };

    loadg(0);
    stores(0);
    __syncthreads();

#pragma unroll 1
    for (int c = 0; c < 8; c++) {
        if (c + 1 < 8) loadg((c + 1) * BKc);
        int buf = c & 1;
#pragma unroll
        for (int kk = 0; kk < BKc; kk += 8) {
            uint32_t af[2][4];
#pragma unroll
            for (int mt = 0; mt < 2; mt++) {
                int rm = wm * 32 + mt * 16;
                af[mt][0] = tf32(As[buf][rm + g][kk + tig]);
                af[mt][1] = tf32(As[buf][rm + g + 8][kk + tig]);
                af[mt][2] = tf32(As[buf][rm + g][kk + tig + 4]);
                af[mt][3] = tf32(As[buf][rm + g + 8][kk + tig + 4]);
            }
#pragma unroll
            for (int nt = 0; nt < 4; nt++) {
                int cn = wn * 32 + nt * 8;
                uint32_t b0[2], b1[2];
                b0[0] = tf32(Bs0[buf][kk + tig][cn + g]);
                b0[1] = tf32(Bs0[buf][kk + tig + 4][cn + g]);
                b1[0] = tf32(Bs1[buf][kk + tig][cn + g]);
                b1[1] = tf32(Bs1[buf][kk + tig + 4][cn + g]);
#pragma unroll
                for (int mt = 0; mt < 2; mt++) {
                    mma_tf32(cfr0[mt][nt], af[mt], b0);
                    mma_tf32(cfr1[mt][nt], af[mt], b1);
                }
            }
            if (do_ed) {
                uint32_t bvd[2];
                int kg = c * BKc + kk;
                bvd[0] = tf32(vds[kg + tig][g]);
                bvd[1] = tf32(vds[kg + tig + 4][g]);
                mma_tf32(edf[0], af[0], bvd);
                mma_tf32(edf[1], af[1], bvd);
            }
        }
        if (c + 1 < 8) stores((c + 1) & 1);
        __syncthreads();
    }

    if (do_ed) {
        auto edst = [&](int m, int col, float v) {
            int rel = col >> 2;
            int h = col & 3;
            float* dst = rel ? edB : edA;
            if (m < M)
                *(float2*)(dst + m * 8 + h * 2) =
                    make_float2(__expf(v), __expf(0.2f * v));
        };
#pragma unroll
        for (int mt = 0; mt < 2; mt++) {
            int m_lo = m0 + wm * 32 + mt * 16 + g;
            int m_hi = m_lo + 8;
            edst(m_lo, 2 * tig + 0, edf[mt][0]);
            edst(m_lo, 2 * tig + 1, edf[mt][1]);
            edst(m_hi, 2 * tig + 0, edf[mt][2]);
            edst(m_hi, 2 * tig + 1, edf[mt][3]);
        }
    }

    // es epilogues for both outputs
    {
        constexpr int NH = 32 / CC;
#pragma unroll
        for (int which = 0; which < 2; which++) {
            const float* a_s = which ? a_s1 : a_s0;
            float* es = which ? esB : esA;
            float pl[2][NH], ph[2][NH];
#pragma unroll
            for (int mt = 0; mt < 2; mt++)
#pragma unroll
                for (int nh = 0; nh < NH; nh++) { pl[mt][nh] = 0.f; ph[mt][nh] = 0.f; }
#pragma unroll
            for (int nt = 0; nt < 4; nt++) {
                int nh = (nt * 8) / CC;
                float w0 = __ldg(&a_s[n0 + wn * 32 + nt * 8 + 2 * tig]);
                float w1 = __ldg(&a_s[n0 + wn * 32 + nt * 8 + 2 * tig + 1]);
#pragma unroll
                for (int mt = 0; mt < 2; mt++) {
                    float c0 = which ? cfr1[mt][nt][0] : cfr0[mt][nt][0];
                    float c1 = which ? cfr1[mt][nt][1] : cfr0[mt][nt][1];
                    float c2 = which ? cfr1[mt][nt][2] : cfr0[mt][nt][2];
                    float c3 = which ? cfr1[mt][nt][3] : cfr0[mt][nt][3];
                    pl[mt][nh] += c0 * w0 + c1 * w1;
                    ph[mt][nh] += c2 * w0 + c3 * w1;
                }
            }
#pragma unroll
            for (int mt = 0; mt < 2; mt++)
#pragma unroll
                for (int nh = 0; nh < NH; nh++) {
#pragma unroll
                    for (int off = 1; off < 4; off <<= 1) {
                        pl[mt][nh] += __shfl_xor_sync(0xffffffffu, pl[mt][nh], off, 4);
                        ph[mt][nh] += __shfl_xor_sync(0xffffffffu, ph[mt][nh], off, 4);
                    }
                    if (tig == 0) {
                        int h = (n0 + wn * 32) / CC + nh;
                        int m_lo = m0 + wm * 32 + mt * 16 + g;
                        int m_hi = m_lo + 8;
                        if (m_lo < M)
                            *(float2*)(es + m_lo * 8 + h * 2) =
                                make_float2(__expf(pl[mt][nh]), __expf(0.2f * pl[mt][nh]));
                        if (m_hi < M)
                            *(float2*)(es + m_hi * 8 + h * 2) =
                                make_float2(__expf(ph[mt][nh]), __expf(0.2f * ph[mt][nh]));
                    }
                }
        }
    }

#pragma unroll
    for (int mt = 0; mt < 2; mt++) {
        int m_lo = m0 + wm * 32 + mt * 16 + g;
        int m_hi = m_lo + 8;
#pragma unroll
        for (int nt = 0; nt < 4; nt++) {
            int col = n0 + wn * 32 + nt * 8 + 2 * tig;
            if (m_lo < M) {
                *(__half2*)(C0 + (size_t)m_lo * N + col) =
                    __floats2half2_rn(cfr0[mt][nt][0], cfr0[mt][nt][1]);
                *(__half2*)(C1 + (size_t)m_lo * N + col) =
                    __floats2half2_rn(cfr1[mt][nt][0], cfr1[mt][nt][1]);
            }
            if (m_hi < M) {
                *(__half2*)(C0 + (size_t)m_hi * N + col) =
                    __floats2half2_rn(cfr0[mt][nt][2], cfr0[mt][nt][3]);
                *(__half2*)(C1 + (size_t)m_hi * N + col) =
                    __floats2half2_rn(cfr1[mt][nt][2], cfr1[mt][nt][3]);
            }
        }
    }
}

// -------- per-relation edge accumulation: batch-8, predicated (R14-best) -------
template <int D>
__device__ __forceinline__ void edge_accum(
        const int* __restrict__ off, const int* __restrict__ srt,
        const float* __restrict__ es, const float* __restrict__ ed,
        const __half* __restrict__ hs,
        int d, int lane, int h, float& den, float* a) {
    int start = __ldg(&off[d]), end = __ldg(&off[d + 1]);
    float2 edv = __ldg((const float2*)(ed + d * 8 + h * 2));
    float E1d = edv.x, E2d = edv.y;
    for (int i = start; i < end; i += 8) {
        int rem = end - i;
        int s[8];
#pragma unroll
        for (int j = 0; j < 8; j++) {
            int idx = (j < rem) ? i + j : i;
            s[j] = __ldg(&srt[idx]);
        }
        float2 v[8];
#pragma unroll
        for (int j = 0; j < 8; j++)
            v[j] = __ldg((const float2*)(es + s[j] * 8 + h * 2));
        if (D == 128) {
            uint2 u[8];
#pragma unroll
            for (int j = 0; j < 8; j++)
                u[j] = *(const uint2*)(hs + (size_t)s[j] * D + lane * 4);
#pragma unroll
            for (int j = 0; j < 8; j++) {
                float ee = (j < rem) ? fmaxf(v[j].x * E1d, v[j].y * E2d) : 0.f;
                den += ee;
                union { uint2 uu; __half2 h2[2]; } cv;
                cv.uu = u[j];
                float2 p0 = __half22float2(cv.h2[0]);
                float2 p1 = __half22float2(cv.h2[1]);
                a[0] += ee * p0.x; a[1] += ee * p0.y;
                a[2] += ee * p1.x; a[3] += ee * p1.y;
            }
        } else {
            unsigned u[8];
#pragma unroll
            for (int j = 0; j < 8; j++)
                u[j] = *(const unsigned*)(hs + (size_t)s[j] * D + lane * 2);
#pragma unroll
            for (int j = 0; j < 8; j++) {
                float ee = (j < rem) ? fmaxf(v[j].x * E1d, v[j].y * E2d) : 0.f;
                den += ee;
                union { unsigned uu; __half2 h2; } cv;
                cv.uu = u[j];
                float2 p = __half22float2(cv.h2);
                a[0] += ee * p.x; a[1] += ee * p.y;
            }
        }
    }
}

// -------- SINGLE gather over all dst nodes -------------------------------------
template <int D>
__global__ void __launch_bounds__(256)
gat_gather_all(const int* __restrict__ off0, const int* __restrict__ srt0,
               const float* __restrict__ es0, const float* __restrict__ ed0,
               const __half* __restrict__ hs0,
               const int* __restrict__ off1, const int* __restrict__ srt1,
               const float* __restrict__ es1, const float* __restrict__ ed1,
               const __half* __restrict__ hs1,
               const int* __restrict__ off2, const int* __restrict__ srt2,
               const float* __restrict__ es2, const float* __restrict__ ed2,
               const __half* __restrict__ hs2,
               float* __restrict__ accP, float* __restrict__ accA,
               const float* __restrict__ bP0, const float* __restrict__ bP1,
               const float* __restrict__ bA0, int relu) {
    constexpr int CPL = D / 32;
    int warp = (blockIdx.x * blockDim.x + threadIdx.x) >> 5;
    int lane = threadIdx.x & 31;
    int h = lane >> 3;
    int cb = lane * CPL;
    if (warp < NP) {
        int d = warp;
        float denA = 0.f, denB = 0.f;
        float aA[4] = {0.f, 0.f, 0.f, 0.f}, aB[4] = {0.f, 0.f, 0.f, 0.f};
        edge_accum<D>(off0, srt0, es0, ed0, hs0, d, lane, h, denA, aA);
        edge_accum<D>(off1, srt1, es1, ed1, hs1, d, lane, h, denB, aB);
        float invA = 1.f / (denA + 1e-16f);
        float invB = 1.f / (denB + 1e-16f);
        float* dp = accP + (size_t)d * D + cb;
        if (D == 128) {
            float4 b0 = *(const float4*)(bP0 + cb);
            float4 b1 = *(const float4*)(bP1 + cb);
            float4 o = make_float4(aA[0] * invA + aB[0] * invB + b0.x + b1.x,
                                   aA[1] * invA + aB[1] * invB + b0.y + b1.y,
                                   aA[2] * invA + aB[2] * invB + b0.z + b1.z,
                                   aA[3] * invA + aB[3] * invB + b0.w + b1.w);
            if (relu) {
                o.x = fmaxf(o.x, 0.f); o.y = fmaxf(o.y, 0.f);
                o.z = fmaxf(o.z, 0.f); o.w = fmaxf(o.w, 0.f);
            }
            *(float4*)dp = o;
        } else {
            float2 b0 = *(const float2*)(bP0 + cb);
            float2 b1 = *(const float2*)(bP1 + cb);
            float2 o = make_float2(aA[0] * invA + aB[0] * invB + b0.x + b1.x,
                                   aA[1] * invA + aB[1] * invB + b0.y + b1.y);
            if (relu) { o.x = fmaxf(o.x, 0.f); o.y = fmaxf(o.y, 0.f); }
            *(float2*)dp = o;
        }
    } else if (warp < NP + NA) {
        int d = warp - NP;
        float den = 0.f;
        float a[4] = {0.f, 0.f, 0.f, 0.f};
        edge_accum<D>(off2, srt2, es2, ed2, hs2, d, lane, h, den, a);
        float inv = 1.f / (den + 1e-16f);
        float* dp = accA + (size_t)d * D + cb;
        if (D == 128) {
            float4 b0 = *(const float4*)(bA0 + cb);
            float4 o = make_float4(a[0] * inv + b0.x, a[1] * inv + b0.y,
                                   a[2] * inv + b0.z, a[3] * inv + b0.w);
            if (relu) {
                o.x = fmaxf(o.x, 0.f); o.y = fmaxf(o.y, 0.f);
                o.z = fmaxf(o.z, 0.f); o.w = fmaxf(o.w, 0.f);
            }
            *(float4*)dp = o;
        } else {
            float2 b0 = *(const float2*)(bA0 + cb);
            float2 o = make_float2(a[0] * inv + b0.x, a[1] * inv + b0.y);
            if (relu) { o.x = fmaxf(o.x, 0.f); o.y = fmaxf(o.y, 0.f); }
            *(float2*)dp = o;
        }
    }
}

// =============================================================================
extern "C" void kernel_launch(void* const* d_in, const int* in_sizes, int n_in,
                              void* d_out, int out_size) {
    const float* x_p = (const float*)d_in[0];
    const float* x_a = (const float*)d_in[1];
    const int* src_pp = (const int*)d_in[2];
    const int* dst_pp = (const int*)d_in[3];
    const int* src_ap = (const int*)d_in[4];
    const int* dst_ap = (const int*)d_in[5];
    const int* src_pa = (const int*)d_in[6];
    const int* dst_pa = (const int*)d_in[7];
    const float* Wsrc1 = (const float*)d_in[8];
    const float* Wdst1 = (const float*)d_in[9];
    const float* asrc1 = (const float*)d_in[10];
    const float* adst1 = (const float*)d_in[11];
    const float* b1 = (const float*)d_in[12];
    const float* Wsrc2 = (const float*)d_in[13];
    const float* Wdst2 = (const float*)d_in[14];
    const float* asrc2 = (const float*)d_in[15];
    const float* adst2 = (const float*)d_in[16];
    const float* b2 = (const float*)d_in[17];
    float* out = (float*)d_out;

    void* p;
    cudaGetSymbolAddress(&p, g_hs0);    __half* hs0 = (__half*)p;
    cudaGetSymbolAddress(&p, g_hs1);    __half* hs1 = (__half*)p;
    cudaGetSymbolAddress(&p, g_hs2);    __half* hs2 = (__half*)p;
    cudaGetSymbolAddress(&p, g_hs0b);   __half* hs0b = (__half*)p;
    cudaGetSymbolAddress(&p, g_hs1b);   __half* hs1b = (__half*)p;
    cudaGetSymbolAddress(&p, g_hs2b);   __half* hs2b = (__half*)p;
    cudaGetSymbolAddress(&p, g_es);     float* es   = (float*)p;
    cudaGetSymbolAddress(&p, g_ed);     float* ed   = (float*)p;
    cudaGetSymbolAddress(&p, g_esb);    float* esb  = (float*)p;
    cudaGetSymbolAddress(&p, g_edb);    float* edb  = (float*)p;
    cudaGetSymbolAddress(&p, g_accp);   float* accp = (float*)p;
    cudaGetSymbolAddress(&p, g_acca);   float* acca = (float*)p;
    cudaGetSymbolAddress(&p, g_vd1);    float* vd1  = (float*)p;
    cudaGetSymbolAddress(&p, g_vd2);    float* vd2  = (float*)p;
    cudaGetSymbolAddress(&p, g_off_pp); int* off_pp = (int*)p;
    cudaGetSymbolAddress(&p, g_off_ap); int* off_ap = (int*)p;
    cudaGetSymbolAddress(&p, g_off_pa); int* off_pa = (int*)p;
    cudaGetSymbolAddress(&p, g_srt);    int* srt    = (int*)p;
    cudaGetSymbolAddress(&p, g_writer); int* writer = (int*)p;

    int* srt_pp = srt;
    int* srt_ap = srt + EPP;
    int* srt_pa = srt + EPP + EAP;

    float* es0 = es, *es1 = es + NP * 8, *es2 = es + 2 * NP * 8;
    float* ed0 = ed, *ed1 = ed + NP * 8, *ed2 = ed + 2 * NP * 8;
    float* es0b = esb, *es1b = esb + NP * 8, *es2b = esb + 2 * NP * 8;
    float* ed0b = edb, *ed1b = edb + NP * 8, *ed2b = edb + 2 * NP * 8;

    const int TB = 256;
    auto blocks = [](long long n) { return (int)((n + 255) / 256); };

    // ---- forked stream: CSR build overlaps with vd + layer-1 GEMMs (R14) ----
    cudaStream_t s2;
    cudaStreamCreateWithFlags(&s2, cudaStreamNonBlocking);
    cudaEvent_t eFork, eJoin;
    cudaEventCreateWithFlags(&eFork, cudaEventDisableTiming);
    cudaEventCreateWithFlags(&eJoin, cudaEventDisableTiming);

    cudaEventRecord(eFork, 0);
    cudaStreamWaitEvent(s2, eFork, 0);

    cudaMemsetAsync(off_pp, 0, (NP + 1) * sizeof(int), s2);
    cudaMemsetAsync(off_ap, 0, (NP + 1) * sizeof(int), s2);
    cudaMemsetAsync(off_pa, 0, (NA + 1) * sizeof(int), s2);
    count3<<<blocks(EPP + EAP + EPA), TB, 0, s2>>>(dst_pp, dst_ap, dst_pa,
                                                   off_pp, off_ap, off_pa);
    scan3<<<3, 1024, 0, s2>>>(off_pp, off_ap, off_pa, writer);
    scatter3<<<blocks(EPP + EAP + EPA), TB, 0, s2>>>(src_pp, dst_pp, src_ap, dst_ap,
                                                     src_pa, dst_pa, writer, srt);
    cudaEventRecord(eJoin, s2);

    // ---- main stream: vd + layer-1 GEMMs ----
    compute_vd<<<blocks(2 * 3 * 128 * 4), TB>>>(Wdst1, adst1, Wdst2, adst2, vd1, vd2);
    {
        dim3 gP(2, (NP + 127) / 128), gA(2, (NA + 127) / 128);
        // dual-B over x_p: rel0 (pp) and rel2 (pa); ed for rel0/rel1 via vd1
        mma_es2<32><<<gP, 256>>>(x_p, Wsrc1 + 0 * 128 * 128, Wsrc1 + 2 * 128 * 128,
                                 hs0, hs2, es0, es2, asrc1 + 0 * 128, asrc1 + 2 * 128,
                                 vd1 + 0 * 512, vd1 + 1 * 512, ed0, ed1, NP, 128);
        // author GEMM: rel1 (ap); ed for rel2 via vd1 r2
        mma_es<32, 1><<<gA, 256>>>(x_a, Wsrc1 + 1 * 128 * 128, hs1, es1, asrc1 + 1 * 128,
                                   vd1 + 2 * 512, nullptr, ed2, nullptr, NA, 128);
    }
    cudaStreamWaitEvent(0, eJoin, 0);

    gat_gather_all<128><<<blocks((long long)(NP + NA) * 32), TB>>>(
        off_pp, srt_pp, es0, ed0, hs0,
        off_ap, srt_ap, es1, ed1, hs1,
        off_pa, srt_pa, es2, ed2, hs2,
        accp, acca, b1 + 0, b1 + 128, b1 + 256, 1);

    // ---------------- layer 2 (D=64) -> d_out ----------------
    {
        dim3 gP(1, (NP + 127) / 128), gA(1, (NA + 127) / 128);
        mma_es2<16><<<gP, 256>>>(accp, Wsrc2 + 0 * 128 * 64, Wsrc2 + 2 * 128 * 64,
                                 hs0b, hs2b, es0b, es2b, asrc2 + 0 * 64, asrc2 + 2 * 64,
                                 vd2 + 0 * 512, vd2 + 1 * 512, ed0b, ed1b, NP, 64);
        mma_es<16, 1><<<gA, 256>>>(acca, Wsrc2 + 1 * 128 * 64, hs1b, es1b, asrc2 + 1 * 64,
                                   vd2 + 2 * 512, nullptr, ed2b, nullptr, NA, 64);
        gat_gather_all<64><<<blocks((long long)(NP + NA) * 32), TB>>>(
            off_pp, srt_pp, es0b, ed0b, hs0b,
            off_ap, srt_ap, es1b, ed1b, hs1b,
            off_pa, srt_pa, es2b, ed2b, hs2b,
            out, out + (size_t)NP * 64, b2 + 0, b2 + 64, b2 + 128, 0);
    }
}

// round 17
// speedup vs baseline: 1.1029x; 1.0613x over previous
#include <cuda_runtime.h>
#include <cuda_bf16.h>
#include <cuda_fp16.h>
#include <cstdint>

#define NP 100000
#define NA 50000
#define EPP 1600000
#define EAP 800000
#define EPA 800000

// ---------------- scratch ----------------------------------------------------
__device__ __align__(16) __half g_hs0[NP * 128];
__device__ __align__(16) __half g_hs1[NA * 128];
__device__ __align__(16) __half g_hs2[NP * 128];
__device__ __align__(16) __half g_hs0b[NP * 64];
__device__ __align__(16) __half g_hs1b[NA * 64];
__device__ __align__(16) __half g_hs2b[NP * 64];
__device__ __align__(16) float g_es[3 * NP * 8];
__device__ __align__(16) float g_ed[3 * NP * 8];
__device__ __align__(16) float g_esb[3 * NP * 8];
__device__ __align__(16) float g_edb[3 * NP * 8];
__device__ __align__(16) float g_accp[NP * 128];
__device__ __align__(16) float g_acca[NA * 128];
__device__ __align__(16) float g_vd1[3 * 512];
__device__ __align__(16) float g_vd2[3 * 512];
// CSR scratch
__device__ int g_off_pp[NP + 1];
__device__ int g_off_ap[NP + 1];
__device__ int g_off_pa[NA + 1];
__device__ int g_srt[EPP + EAP + EPA];
__device__ int g_writer[NP + NP + NA];

// ---------------- helpers ----------------------------------------------------
__device__ __forceinline__ uint32_t tf32(float x) {
    uint32_t r;
    asm("cvt.rna.tf32.f32 %0, %1;" : "=r"(r) : "f"(x));
    return r;
}
__device__ __forceinline__ void mma_tf32(float* d, const uint32_t* a, const uint32_t* b) {
    asm("mma.sync.aligned.m16n8k8.row.col.f32.tf32.tf32.f32 "
        "{%0,%1,%2,%3},{%4,%5,%6,%7},{%8,%9},{%0,%1,%2,%3};"
        : "+f"(d[0]), "+f"(d[1]), "+f"(d[2]), "+f"(d[3])
        : "r"(a[0]), "r"(a[1]), "r"(a[2]), "r"(a[3]), "r"(b[0]), "r"(b[1]));
}

// ---------------- batched CSR build -------------------------------------------
__global__ void count3(const int* __restrict__ d0, const int* __restrict__ d1,
                       const int* __restrict__ d2, int* __restrict__ o0,
                       int* __restrict__ o1, int* __restrict__ o2) {
    int i = blockIdx.x * blockDim.x + threadIdx.x;
    if (i < EPP) atomicAdd(&o0[d0[i] + 1], 1);
    else if (i < EPP + EAP) atomicAdd(&o1[d1[i - EPP] + 1], 1);
    else if (i < EPP + EAP + EPA) atomicAdd(&o2[d2[i - EPP - EAP] + 1], 1);
}
__device__ void scan_one(int* __restrict__ off, int* __restrict__ writer, int n, int nw) {
    __shared__ int ssum[1024];
    int tid = threadIdx.x;
    int running = 0;
    for (int base = 0; base < n; base += 4096) {
        int idx = base + tid * 4;
        int v0 = idx + 0 < n ? off[idx + 0] : 0;
        int v1 = idx + 1 < n ? off[idx + 1] : 0;
        int v2 = idx + 2 < n ? off[idx + 2] : 0;
        int v3 = idx + 3 < n ? off[idx + 3] : 0;
        int p0 = v0, p1 = p0 + v1, p2 = p1 + v2, p3 = p2 + v3;
        ssum[tid] = p3;
        __syncthreads();
        for (int o = 1; o < 1024; o <<= 1) {
            int val = 0;
            if (tid >= o) val = ssum[tid - o];
            __syncthreads();
            if (tid >= o) ssum[tid] += val;
            __syncthreads();
        }
        int excl = running + (tid ? ssum[tid - 1] : 0);
        int total = ssum[1023];
        __syncthreads();
        int s0 = excl + p0, s1 = excl + p1, s2 = excl + p2, s3 = excl + p3;
        if (idx + 0 < n) { off[idx + 0] = s0; if (idx + 0 < nw) writer[idx + 0] = s0; }
        if (idx + 1 < n) { off[idx + 1] = s1; if (idx + 1 < nw) writer[idx + 1] = s1; }
        if (idx + 2 < n) { off[idx + 2] = s2; if (idx + 2 < nw) writer[idx + 2] = s2; }
        if (idx + 3 < n) { off[idx + 3] = s3; if (idx + 3 < nw) writer[idx + 3] = s3; }
        running += total;
    }
}
__global__ void __launch_bounds__(1024)
scan3(int* __restrict__ o0, int* __restrict__ o1, int* __restrict__ o2,
      int* __restrict__ writer) {
    if (blockIdx.x == 0)      scan_one(o0, writer, NP + 1, NP);
    else if (blockIdx.x == 1) scan_one(o1, writer + NP, NP + 1, NP);
    else                      scan_one(o2, writer + 2 * NP, NA + 1, NA);
}
__global__ void scatter3(const int* __restrict__ s0, const int* __restrict__ d0,
                         const int* __restrict__ s1, const int* __restrict__ d1,
                         const int* __restrict__ s2, const int* __restrict__ d2,
                         int* __restrict__ writer, int* __restrict__ srt) {
    int i = blockIdx.x * blockDim.x + threadIdx.x;
    if (i < EPP) {
        int pos = atomicAdd(&writer[d0[i]], 1);
        srt[pos] = s0[i];
    } else if (i < EPP + EAP) {
        int e = i - EPP;
        int pos = atomicAdd(&writer[NP + d1[e]], 1);
        srt[EPP + pos] = s1[e];
    } else if (i < EPP + EAP + EPA) {
        int e = i - EPP - EAP;
        int pos = atomicAdd(&writer[2 * NP + d2[e]], 1);
        srt[EPP + EAP + pos] = s2[e];
    }
}

// ---------------- vd folding ---------------------------------------------------
__global__ void compute_vd(const float* __restrict__ Wd1, const float* __restrict__ ad1,
                           const float* __restrict__ Wd2, const float* __restrict__ ad2,
                           float* __restrict__ vd1, float* __restrict__ vd2) {
    int i = blockIdx.x * blockDim.x + threadIdx.x;
    if (i >= 2 * 3 * 128 * 4) return;
    int layer = i >= 3 * 128 * 4;
    int ii = i - layer * 3 * 128 * 4;
    int h = ii & 3;
    int f = (ii >> 2) & 127;
    int r = ii >> 9;
    int D = layer ? 64 : 128;
    int C = D / 4;
    const float* W = (layer ? Wd2 : Wd1) + (size_t)r * 128 * D + (size_t)f * D + h * C;
    const float* a = (layer ? ad2 : ad1) + r * 4 * C + h * C;
    float s = 0.f;
    for (int c = 0; c < C; c++) s += W[c] * a[c];
    (layer ? vd2 : vd1)[r * 512 + f * 4 + h] = s;
}

// ============== tf32 MMA GEMM, SINGLE B (author relations), fused ed ==========
template <int CC, int NED>
__global__ void __launch_bounds__(256)
mma_es(const float* __restrict__ A, const float* __restrict__ B,
       __half* __restrict__ C, float* __restrict__ es,
       const float* __restrict__ a_s,
       const float* __restrict__ vdA, const float* __restrict__ vdB,
       float* __restrict__ edA, float* __restrict__ edB,
       int M, int N) {
    const int K = 128;
    const int BKc = 16;
    __shared__ __align__(16) float As[2][128][BKc + 4];
    __shared__ __align__(16) float Bs[2][BKc][64 + 8];
    __shared__ __align__(16) float vds[128][8];
    int tid = threadIdx.x;
    int lane = tid & 31, wid = tid >> 5;
    int wm = wid & 3, wn = wid >> 2;
    int g = lane >> 2, tig = lane & 3;
    int m0 = blockIdx.y * 128, n0 = blockIdx.x * 64;

    if (NED > 0) {
        for (int i = tid; i < 1024; i += 256) {
            int k = i >> 3, j = i & 7;
            float v = 0.f;
            if (j < 4) v = vdA[k * 4 + j];
            else if (NED == 2) v = vdB[k * 4 + (j - 4)];
            vds[k][j] = v;
        }
    }

    float cfr[2][4][4];
#pragma unroll
    for (int mt = 0; mt < 2; mt++)
#pragma unroll
        for (int nt = 0; nt < 4; nt++)
#pragma unroll
            for (int q = 0; q < 4; q++) cfr[mt][nt][q] = 0.f;
    float edf[2][4];
#pragma unroll
    for (int mt = 0; mt < 2; mt++)
#pragma unroll
        for (int q = 0; q < 4; q++) edf[mt][q] = 0.f;
    bool do_ed = (NED > 0) && (wn == 0) && (blockIdx.x == 0);

    int aRow = tid >> 1, aK = (tid & 1) * 8;
    int bRow = tid >> 4, bC = (tid & 15) * 4;

    float4 ra0, ra1, rb;
    auto loadg = [&](int k0) {
        int m = m0 + aRow;
        if (m < M) {
            ra0 = *(const float4*)(A + (size_t)m * K + k0 + aK);
            ra1 = *(const float4*)(A + (size_t)m * K + k0 + aK + 4);
        } else {
            ra0 = make_float4(0.f, 0.f, 0.f, 0.f);
            ra1 = ra0;
        }
        rb = *(const float4*)(B + (size_t)(k0 + bRow) * N + n0 + bC);
    };
    auto stores = [&](int buf) {
        *(float4*)&As[buf][aRow][aK] = ra0;
        *(float4*)&As[buf][aRow][aK + 4] = ra1;
        *(float4*)&Bs[buf][bRow][bC] = rb;
    };

    loadg(0);
    stores(0);
    __syncthreads();

#pragma unroll 1
    for (int c = 0; c < 8; c++) {
        if (c + 1 < 8) loadg((c + 1) * BKc);
        int buf = c & 1;
#pragma unroll
        for (int kk = 0; kk < BKc; kk += 8) {
            uint32_t af[2][4], bf[4][2];
#pragma unroll
            for (int mt = 0; mt < 2; mt++) {
                int rm = wm * 32 + mt * 16;
                af[mt][0] = tf32(As[buf][rm + g][kk + tig]);
                af[mt][1] = tf32(As[buf][rm + g + 8][kk + tig]);
                af[mt][2] = tf32(As[buf][rm + g][kk + tig + 4]);
                af[mt][3] = tf32(As[buf][rm + g + 8][kk + tig + 4]);
            }
#pragma unroll
            for (int nt = 0; nt < 4; nt++) {
                int cn = wn * 32 + nt * 8;
                bf[nt][0] = tf32(Bs[buf][kk + tig][cn + g]);
                bf[nt][1] = tf32(Bs[buf][kk + tig + 4][cn + g]);
            }
#pragma unroll
            for (int mt = 0; mt < 2; mt++)
#pragma unroll
                for (int nt = 0; nt < 4; nt++)
                    mma_tf32(cfr[mt][nt], af[mt], bf[nt]);
            if (do_ed) {
                uint32_t bvd[2];
                int kg = c * BKc + kk;
                bvd[0] = tf32(vds[kg + tig][g]);
                bvd[1] = tf32(vds[kg + tig + 4][g]);
                mma_tf32(edf[0], af[0], bvd);
                mma_tf32(edf[1], af[1], bvd);
            }
        }
        if (c + 1 < 8) stores((c + 1) & 1);
        __syncthreads();
    }

    if (do_ed) {
        auto edst = [&](int m, int col, float v) {
            int rel = col >> 2;
            if (rel == 1 && NED < 2) return;
            int h = col & 3;
            float* dst = rel ? edB : edA;
            if (m < M)
                *(float2*)(dst + m * 8 + h * 2) =
                    make_float2(__expf(v), __expf(0.2f * v));
        };
#pragma unroll
        for (int mt = 0; mt < 2; mt++) {
            int m_lo = m0 + wm * 32 + mt * 16 + g;
            int m_hi = m_lo + 8;
            edst(m_lo, 2 * tig + 0, edf[mt][0]);
            edst(m_lo, 2 * tig + 1, edf[mt][1]);
            edst(m_hi, 2 * tig + 0, edf[mt][2]);
            edst(m_hi, 2 * tig + 1, edf[mt][3]);
        }
    }

    {
        constexpr int NH = 32 / CC;
        float pl[2][NH], ph[2][NH];
#pragma unroll
        for (int mt = 0; mt < 2; mt++)
#pragma unroll
            for (int nh = 0; nh < NH; nh++) { pl[mt][nh] = 0.f; ph[mt][nh] = 0.f; }
#pragma unroll
        for (int nt = 0; nt < 4; nt++) {
            int nh = (nt * 8) / CC;
            float w0 = __ldg(&a_s[n0 + wn * 32 + nt * 8 + 2 * tig]);
            float w1 = __ldg(&a_s[n0 + wn * 32 + nt * 8 + 2 * tig + 1]);
#pragma unroll
            for (int mt = 0; mt < 2; mt++) {
                pl[mt][nh] += cfr[mt][nt][0] * w0 + cfr[mt][nt][1] * w1;
                ph[mt][nh] += cfr[mt][nt][2] * w0 + cfr[mt][nt][3] * w1;
            }
        }
#pragma unroll
        for (int mt = 0; mt < 2; mt++)
#pragma unroll
            for (int nh = 0; nh < NH; nh++) {
#pragma unroll
                for (int off = 1; off < 4; off <<= 1) {
                    pl[mt][nh] += __shfl_xor_sync(0xffffffffu, pl[mt][nh], off, 4);
                    ph[mt][nh] += __shfl_xor_sync(0xffffffffu, ph[mt][nh], off, 4);
                }
                if (tig == 0) {
                    int h = (n0 + wn * 32) / CC + nh;
                    int m_lo = m0 + wm * 32 + mt * 16 + g;
                    int m_hi = m_lo + 8;
                    if (m_lo < M)
                        *(float2*)(es + m_lo * 8 + h * 2) =
                            make_float2(__expf(pl[mt][nh]), __expf(0.2f * pl[mt][nh]));
                    if (m_hi < M)
                        *(float2*)(es + m_hi * 8 + h * 2) =
                            make_float2(__expf(ph[mt][nh]), __expf(0.2f * ph[mt][nh]));
                }
            }
    }

#pragma unroll
    for (int mt = 0; mt < 2; mt++) {
        int m_lo = m0 + wm * 32 + mt * 16 + g;
        int m_hi = m_lo + 8;
#pragma unroll
        for (int nt = 0; nt < 4; nt++) {
            int col = n0 + wn * 32 + nt * 8 + 2 * tig;
            if (m_lo < M)
                *(__half2*)(C + (size_t)m_lo * N + col) =
                    __floats2half2_rn(cfr[mt][nt][0], cfr[mt][nt][1]);
            if (m_hi < M)
                *(__half2*)(C + (size_t)m_hi * N + col) =
                    __floats2half2_rn(cfr[mt][nt][2], cfr[mt][nt][3]);
        }
    }
}

// ============== DUAL-B tf32 MMA GEMM (paper relations, shared A) ==============
template <int CC>
__global__ void __launch_bounds__(256)
mma_es2(const float* __restrict__ A,
        const float* __restrict__ B0, const float* __restrict__ B1,
        __half* __restrict__ C0, __half* __restrict__ C1,
        float* __restrict__ esA, float* __restrict__ esB,
        const float* __restrict__ a_s0, const float* __restrict__ a_s1,
        const float* __restrict__ vdA, const float* __restrict__ vdB,
        float* __restrict__ edA, float* __restrict__ edB,
        int M, int N) {
    const int K = 128;
    const int BKc = 16;
    __shared__ __align__(16) float As[2][128][BKc + 4];
    __shared__ __align__(16) float Bs0[2][BKc][64 + 8];
    __shared__ __align__(16) float Bs1[2][BKc][64 + 8];
    __shared__ __align__(16) float vds[128][8];
    int tid = threadIdx.x;
    int lane = tid & 31, wid = tid >> 5;
    int wm = wid & 3, wn = wid >> 2;
    int g = lane >> 2, tig = lane & 3;
    int m0 = blockIdx.y * 128, n0 = blockIdx.x * 64;

    for (int i = tid; i < 1024; i += 256) {
        int k = i >> 3, j = i & 7;
        vds[k][j] = (j < 4) ? vdA[k * 4 + j] : vdB[k * 4 + (j - 4)];
    }

    float cfr0[2][4][4], cfr1[2][4][4];
#pragma unroll
    for (int mt = 0; mt < 2; mt++)
#pragma unroll
        for (int nt = 0; nt < 4; nt++)
#pragma unroll
            for (int q = 0; q < 4; q++) { cfr0[mt][nt][q] = 0.f; cfr1[mt][nt][q] = 0.f; }
    float edf[2][4];
#pragma unroll
    for (int mt = 0; mt < 2; mt++)
#pragma unroll
        for (int q = 0; q < 4; q++) edf[mt][q] = 0.f;
    bool do_ed = (wn == 0) && (blockIdx.x == 0);

    int aRow = tid >> 1, aK = (tid & 1) * 8;
    int bRow = tid >> 4, bC = (tid & 15) * 4;

    float4 ra0, ra1, rb0, rb1;
    auto loadg = [&](int k0) {
        int m = m0 + aRow;
        if (m < M) {
            ra0 = *(const float4*)(A + (size_t)m * K + k0 + aK);
            ra1 = *(const float4*)(A + (size_t)m * K + k0 + aK + 4);
        } else {
            ra0 = make_float4(0.f, 0.f, 0.f, 0.f);
            ra1 = ra0;
        }
        rb0 = *(const float4*)(B0 + (size_t)(k0 + bRow) * N + n0 + bC);
        rb1 = *(const float4*)(B1 + (size_t)(k0 + bRow) * N + n0 + bC);
    };
    auto stores = [&](int buf) {
        *(float4*)&As[buf][aRow][aK] = ra0;
        *(float4*)&As[buf][aRow][aK + 4] = ra1;
        *(float4*)&Bs0[buf][bRow][bC] = rb0;
        *(float4*)&Bs1[buf][bRow][bC] = rb1;
    };

    loadg(0);
    stores(0);
    __syncthreads();

#pragma unroll 1
    for (int c = 0; c < 8; c++) {
        if (c + 1 < 8) loadg((c + 1) * BKc);
        int buf = c & 1;
#pragma unroll
        for (int kk = 0; kk < BKc; kk += 8) {
            uint32_t af[2][4];
#pragma unroll
            for (int mt = 0; mt < 2; mt++) {
                int rm = wm * 32 + mt * 16;
                af[mt][0] = tf32(As[buf][rm + g][kk + tig]);
                af[mt][1] = tf32(As[buf][rm + g + 8][kk + tig]);
                af[mt][2] = tf32(As[buf][rm + g][kk + tig + 4]);
                af[mt][3] = tf32(As[buf][rm + g + 8][kk + tig + 4]);
            }
#pragma unroll
            for (int nt = 0; nt < 4; nt++) {
                int cn = wn * 32 + nt * 8;
                uint32_t b0[2], b1[2];
                b0[0] = tf32(Bs0[buf][kk + tig][cn + g]);
                b0[1] = tf32(Bs0[buf][kk + tig + 4][cn + g]);
                b1[0] = tf32(Bs1[buf][kk + tig][cn + g]);
                b1[1] = tf32(Bs1[buf][kk + tig + 4][cn + g]);
#pragma unroll
                for (int mt = 0; mt < 2; mt++) {
                    mma_tf32(cfr0[mt][nt], af[mt], b0);
                    mma_tf32(cfr1[mt][nt], af[mt], b1);
                }
            }
            if (do_ed) {
                uint32_t bvd[2];
                int kg = c * BKc + kk;
                bvd[0] = tf32(vds[kg + tig][g]);
                bvd[1] = tf32(vds[kg + tig + 4][g]);
                mma_tf32(edf[0], af[0], bvd);
                mma_tf32(edf[1], af[1], bvd);
            }
        }
        if (c + 1 < 8) stores((c + 1) & 1);
        __syncthreads();
    }

    if (do_ed) {
        auto edst = [&](int m, int col, float v) {
            int rel = col >> 2;
            int h = col & 3;
            float* dst = rel ? edB : edA;
            if (m < M)
                *(float2*)(dst + m * 8 + h * 2) =
                    make_float2(__expf(v), __expf(0.2f * v));
        };
#pragma unroll
        for (int mt = 0; mt < 2; mt++) {
            int m_lo = m0 + wm * 32 + mt * 16 + g;
            int m_hi = m_lo + 8;
            edst(m_lo, 2 * tig + 0, edf[mt][0]);
            edst(m_lo, 2 * tig + 1, edf[mt][1]);
            edst(m_hi, 2 * tig + 0, edf[mt][2]);
            edst(m_hi, 2 * tig + 1, edf[mt][3]);
        }
    }

    {
        constexpr int NH = 32 / CC;
#pragma unroll
        for (int which = 0; which < 2; which++) {
            const float* a_s = which ? a_s1 : a_s0;
            float* es = which ? esB : esA;
            float pl[2][NH], ph[2][NH];
#pragma unroll
            for (int mt = 0; mt < 2; mt++)
#pragma unroll
                for (int nh = 0; nh < NH; nh++) { pl[mt][nh] = 0.f; ph[mt][nh] = 0.f; }
#pragma unroll
            for (int nt = 0; nt < 4; nt++) {
                int nh = (nt * 8) / CC;
                float w0 = __ldg(&a_s[n0 + wn * 32 + nt * 8 + 2 * tig]);
                float w1 = __ldg(&a_s[n0 + wn * 32 + nt * 8 + 2 * tig + 1]);
#pragma unroll
                for (int mt = 0; mt < 2; mt++) {
                    float c0 = which ? cfr1[mt][nt][0] : cfr0[mt][nt][0];
                    float c1 = which ? cfr1[mt][nt][1] : cfr0[mt][nt][1];
                    float c2 = which ? cfr1[mt][nt][2] : cfr0[mt][nt][2];
                    float c3 = which ? cfr1[mt][nt][3] : cfr0[mt][nt][3];
                    pl[mt][nh] += c0 * w0 + c1 * w1;
                    ph[mt][nh] += c2 * w0 + c3 * w1;
                }
            }
#pragma unroll
            for (int mt = 0; mt < 2; mt++)
#pragma unroll
                for (int nh = 0; nh < NH; nh++) {
#pragma unroll
                    for (int off = 1; off < 4; off <<= 1) {
                        pl[mt][nh] += __shfl_xor_sync(0xffffffffu, pl[mt][nh], off, 4);
                        ph[mt][nh] += __shfl_xor_sync(0xffffffffu, ph[mt][nh], off, 4);
                    }
                    if (tig == 0) {
                        int h = (n0 + wn * 32) / CC + nh;
                        int m_lo = m0 + wm * 32 + mt * 16 + g;
                        int m_hi = m_lo + 8;
                        if (m_lo < M)
                            *(float2*)(es + m_lo * 8 + h * 2) =
                                make_float2(__expf(pl[mt][nh]), __expf(0.2f * pl[mt][nh]));
                        if (m_hi < M)
                            *(float2*)(es + m_hi * 8 + h * 2) =
                                make_float2(__expf(ph[mt][nh]), __expf(0.2f * ph[mt][nh]));
                    }
                }
        }
    }

#pragma unroll
    for (int mt = 0; mt < 2; mt++) {
        int m_lo = m0 + wm * 32 + mt * 16 + g;
        int m_hi = m_lo + 8;
#pragma unroll
        for (int nt = 0; nt < 4; nt++) {
            int col = n0 + wn * 32 + nt * 8 + 2 * tig;
            if (m_lo < M) {
                *(__half2*)(C0 + (size_t)m_lo * N + col) =
                    __floats2half2_rn(cfr0[mt][nt][0], cfr0[mt][nt][1]);
                *(__half2*)(C1 + (size_t)m_lo * N + col) =
                    __floats2half2_rn(cfr1[mt][nt][0], cfr1[mt][nt][1]);
            }
            if (m_hi < M) {
                *(__half2*)(C0 + (size_t)m_hi * N + col) =
                    __floats2half2_rn(cfr0[mt][nt][2], cfr0[mt][nt][3]);
                *(__half2*)(C1 + (size_t)m_hi * N + col) =
                    __floats2half2_rn(cfr1[mt][nt][2], cfr1[mt][nt][3]);
            }
        }
    }
}

// -------- PAIRED edge accumulation: half-warp per edge, 2 edges per LDG --------
// Lane = (half, hl): half-warp `half` handles edges i+2j+half; lane owns D/16
// channels (cb = hl * D/16), head h = hl>>2. Cross-half combine via shfl_xor(16).
template <int D>
__device__ __forceinline__ void edge_accum(
        const int* __restrict__ off, const int* __restrict__ srt,
        const float* __restrict__ es, const float* __restrict__ ed,
        const __half* __restrict__ hs,
        int d, int hl, int half, float& den, float* a) {
    constexpr int CPL = D / 16;
    int start = __ldg(&off[d]), end = __ldg(&off[d + 1]);
    if (start >= end) return;
    int h = hl >> 2;
    float2 edv = __ldg((const float2*)(ed + d * 8 + h * 2));
    float E1 = edv.x, E2 = edv.y;
    for (int i = start; i < end; i += 8) {   // 4 pairs = 8 edges
        int e[4], s[4];
#pragma unroll
        for (int j = 0; j < 4; j++) {
            e[j] = i + 2 * j + half;
            int idx = (e[j] < end) ? e[j] : start;
            s[j] = __ldg(&srt[idx]);
        }
        float2 v[4];
#pragma unroll
        for (int j = 0; j < 4; j++)
            v[j] = __ldg((const float2*)(es + s[j] * 8 + h * 2));
        if (D == 128) {
            uint4 u[4];
#pragma unroll
            for (int j = 0; j < 4; j++)
                u[j] = *(const uint4*)(hs + (size_t)s[j] * 128 + hl * 8);
#pragma unroll
            for (int j = 0; j < 4; j++) {
                float ee = (e[j] < end) ? fmaxf(v[j].x * E1, v[j].y * E2) : 0.f;
                den += ee;
                union { uint4 q; __half2 h2[4]; } cv; cv.q = u[j];
                float2 p;
                p = __half22float2(cv.h2[0]); a[0] += ee * p.x; a[1] += ee * p.y;
                p = __half22float2(cv.h2[1]); a[2] += ee * p.x; a[3] += ee * p.y;
                p = __half22float2(cv.h2[2]); a[4] += ee * p.x; a[5] += ee * p.y;
                p = __half22float2(cv.h2[3]); a[6] += ee * p.x; a[7] += ee * p.y;
            }
        } else {
            uint2 u[4];
#pragma unroll
            for (int j = 0; j < 4; j++)
                u[j] = *(const uint2*)(hs + (size_t)s[j] * 64 + hl * 4);
#pragma unroll
            for (int j = 0; j < 4; j++) {
                float ee = (e[j] < end) ? fmaxf(v[j].x * E1, v[j].y * E2) : 0.f;
                den += ee;
                union { uint2 q; __half2 h2[2]; } cv; cv.q = u[j];
                float2 p;
                p = __half22float2(cv.h2[0]); a[0] += ee * p.x; a[1] += ee * p.y;
                p = __half22float2(cv.h2[1]); a[2] += ee * p.x; a[3] += ee * p.y;
            }
        }
    }
    (void)CPL;
}

__device__ __forceinline__ void combine16(float& x) {
    x += __shfl_xor_sync(0xffffffffu, x, 16);
}

// -------- SINGLE gather over all dst nodes -------------------------------------
template <int D>
__global__ void __launch_bounds__(256)
gat_gather_all(const int* __restrict__ off0, const int* __restrict__ srt0,
               const float* __restrict__ es0, const float* __restrict__ ed0,
               const __half* __restrict__ hs0,
               const int* __restrict__ off1, const int* __restrict__ srt1,
               const float* __restrict__ es1, const float* __restrict__ ed1,
               const __half* __restrict__ hs1,
               const int* __restrict__ off2, const int* __restrict__ srt2,
               const float* __restrict__ es2, const float* __restrict__ ed2,
               const __half* __restrict__ hs2,
               float* __restrict__ accP, float* __restrict__ accA,
               const float* __restrict__ bP0, const float* __restrict__ bP1,
               const float* __restrict__ bA0, int relu) {
    constexpr int CPL = D / 16;            // channels per lane (half-warp split)
    int warp = (blockIdx.x * blockDim.x + threadIdx.x) >> 5;
    int lane = threadIdx.x & 31;
    int hl = lane & 15, half = lane >> 4;
    int cb = hl * CPL;
    if (warp < NP) {
        int d = warp;
        float denA = 0.f, denB = 0.f;
        float aA[CPL], aB[CPL];
#pragma unroll
        for (int k = 0; k < CPL; k++) { aA[k] = 0.f; aB[k] = 0.f; }
        edge_accum<D>(off0, srt0, es0, ed0, hs0, d, hl, half, denA, aA);
        edge_accum<D>(off1, srt1, es1, ed1, hs1, d, hl, half, denB, aB);
        combine16(denA);
        combine16(denB);
#pragma unroll
        for (int k = 0; k < CPL; k++) { combine16(aA[k]); combine16(aB[k]); }
        if (half == 0) {
            float invA = 1.f / (denA + 1e-16f);
            float invB = 1.f / (denB + 1e-16f);
            float* dp = accP + (size_t)d * D + cb;
#pragma unroll
            for (int q = 0; q < CPL / 4; q++) {
                float4 b0 = *(const float4*)(bP0 + cb + q * 4);
                float4 b1 = *(const float4*)(bP1 + cb + q * 4);
                float4 o = make_float4(
                    aA[q * 4 + 0] * invA + aB[q * 4 + 0] * invB + b0.x + b1.x,
                    aA[q * 4 + 1] * invA + aB[q * 4 + 1] * invB + b0.y + b1.y,
                    aA[q * 4 + 2] * invA + aB[q * 4 + 2] * invB + b0.z + b1.z,
                    aA[q * 4 + 3] * invA + aB[q * 4 + 3] * invB + b0.w + b1.w);
                if (relu) {
                    o.x = fmaxf(o.x, 0.f); o.y = fmaxf(o.y, 0.f);
                    o.z = fmaxf(o.z, 0.f); o.w = fmaxf(o.w, 0.f);
                }
                *(float4*)(dp + q * 4) = o;
            }
        }
    } else if (warp < NP + NA) {
        int d = warp - NP;
        float den = 0.f;
        float a[CPL];
#pragma unroll
        for (int k = 0; k < CPL; k++) a[k] = 0.f;
        edge_accum<D>(off2, srt2, es2, ed2, hs2, d, hl, half, den, a);
        combine16(den);
#pragma unroll
        for (int k = 0; k < CPL; k++) combine16(a[k]);
        if (half == 0) {
            float inv = 1.f / (den + 1e-16f);
            float* dp = accA + (size_t)d * D + cb;
#pragma unroll
            for (int q = 0; q < CPL / 4; q++) {
                float4 b0 = *(const float4*)(bA0 + cb + q * 4);
                float4 o = make_float4(a[q * 4 + 0] * inv + b0.x,
                                       a[q * 4 + 1] * inv + b0.y,
                                       a[q * 4 + 2] * inv + b0.z,
                                       a[q * 4 + 3] * inv + b0.w);
                if (relu) {
                    o.x = fmaxf(o.x, 0.f); o.y = fmaxf(o.y, 0.f);
                    o.z = fmaxf(o.z, 0.f); o.w = fmaxf(o.w, 0.f);
                }
                *(float4*)(dp + q * 4) = o;
            }
        }
    }
}

// =============================================================================
extern "C" void kernel_launch(void* const* d_in, const int* in_sizes, int n_in,
                              void* d_out, int out_size) {
    const float* x_p = (const float*)d_in[0];
    const float* x_a = (const float*)d_in[1];
    const int* src_pp = (const int*)d_in[2];
    const int* dst_pp = (const int*)d_in[3];
    const int* src_ap = (const int*)d_in[4];
    const int* dst_ap = (const int*)d_in[5];
    const int* src_pa = (const int*)d_in[6];
    const int* dst_pa = (const int*)d_in[7];
    const float* Wsrc1 = (const float*)d_in[8];
    const float* Wdst1 = (const float*)d_in[9];
    const float* asrc1 = (const float*)d_in[10];
    const float* adst1 = (const float*)d_in[11];
    const float* b1 = (const float*)d_in[12];
    const float* Wsrc2 = (const float*)d_in[13];
    const float* Wdst2 = (const float*)d_in[14];
    const float* asrc2 = (const float*)d_in[15];
    const float* adst2 = (const float*)d_in[16];
    const float* b2 = (const float*)d_in[17];
    float* out = (float*)d_out;

    void* p;
    cudaGetSymbolAddress(&p, g_hs0);    __half* hs0 = (__half*)p;
    cudaGetSymbolAddress(&p, g_hs1);    __half* hs1 = (__half*)p;
    cudaGetSymbolAddress(&p, g_hs2);    __half* hs2 = (__half*)p;
    cudaGetSymbolAddress(&p, g_hs0b);   __half* hs0b = (__half*)p;
    cudaGetSymbolAddress(&p, g_hs1b);   __half* hs1b = (__half*)p;
    cudaGetSymbolAddress(&p, g_hs2b);   __half* hs2b = (__half*)p;
    cudaGetSymbolAddress(&p, g_es);     float* es   = (float*)p;
    cudaGetSymbolAddress(&p, g_ed);     float* ed   = (float*)p;
    cudaGetSymbolAddress(&p, g_esb);    float* esb  = (float*)p;
    cudaGetSymbolAddress(&p, g_edb);    float* edb  = (float*)p;
    cudaGetSymbolAddress(&p, g_accp);   float* accp = (float*)p;
    cudaGetSymbolAddress(&p, g_acca);   float* acca = (float*)p;
    cudaGetSymbolAddress(&p, g_vd1);    float* vd1  = (float*)p;
    cudaGetSymbolAddress(&p, g_vd2);    float* vd2  = (float*)p;
    cudaGetSymbolAddress(&p, g_off_pp); int* off_pp = (int*)p;
    cudaGetSymbolAddress(&p, g_off_ap); int* off_ap = (int*)p;
    cudaGetSymbolAddress(&p, g_off_pa); int* off_pa = (int*)p;
    cudaGetSymbolAddress(&p, g_srt);    int* srt    = (int*)p;
    cudaGetSymbolAddress(&p, g_writer); int* writer = (int*)p;

    int* srt_pp = srt;
    int* srt_ap = srt + EPP;
    int* srt_pa = srt + EPP + EAP;

    float* es0 = es, *es1 = es + NP * 8, *es2 = es + 2 * NP * 8;
    float* ed0 = ed, *ed1 = ed + NP * 8, *ed2 = ed + 2 * NP * 8;
    float* es0b = esb, *es1b = esb + NP * 8, *es2b = esb + 2 * NP * 8;
    float* ed0b = edb, *ed1b = edb + NP * 8, *ed2b = edb + 2 * NP * 8;

    const int TB = 256;
    auto blocks = [](long long n) { return (int)((n + 255) / 256); };

    // ---- forked stream: CSR build overlaps with vd + layer-1 GEMMs ----
    cudaStream_t s2;
    cudaStreamCreateWithFlags(&s2, cudaStreamNonBlocking);
    cudaEvent_t eFork, eJoin;
    cudaEventCreateWithFlags(&eFork, cudaEventDisableTiming);
    cudaEventCreateWithFlags(&eJoin, cudaEventDisableTiming);

    cudaEventRecord(eFork, 0);
    cudaStreamWaitEvent(s2, eFork, 0);

    cudaMemsetAsync(off_pp, 0, (NP + 1) * sizeof(int), s2);
    cudaMemsetAsync(off_ap, 0, (NP + 1) * sizeof(int), s2);
    cudaMemsetAsync(off_pa, 0, (NA + 1) * sizeof(int), s2);
    count3<<<blocks(EPP + EAP + EPA), TB, 0, s2>>>(dst_pp, dst_ap, dst_pa,
                                                   off_pp, off_ap, off_pa);
    scan3<<<3, 1024, 0, s2>>>(off_pp, off_ap, off_pa, writer);
    scatter3<<<blocks(EPP + EAP + EPA), TB, 0, s2>>>(src_pp, dst_pp, src_ap, dst_ap,
                                                     src_pa, dst_pa, writer, srt);
    cudaEventRecord(eJoin, s2);

    // ---- main stream: vd + layer-1 GEMMs ----
    compute_vd<<<blocks(2 * 3 * 128 * 4), TB>>>(Wdst1, adst1, Wdst2, adst2, vd1, vd2);
    {
        dim3 gP(2, (NP + 127) / 128), gA(2, (NA + 127) / 128);
        mma_es2<32><<<gP, 256>>>(x_p, Wsrc1 + 0 * 128 * 128, Wsrc1 + 2 * 128 * 128,
                                 hs0, hs2, es0, es2, asrc1 + 0 * 128, asrc1 + 2 * 128,
                                 vd1 + 0 * 512, vd1 + 1 * 512, ed0, ed1, NP, 128);
        mma_es<32, 1><<<gA, 256>>>(x_a, Wsrc1 + 1 * 128 * 128, hs1, es1, asrc1 + 1 * 128,
                                   vd1 + 2 * 512, nullptr, ed2, nullptr, NA, 128);
    }
    cudaStreamWaitEvent(0, eJoin, 0);

    gat_gather_all<128><<<blocks((long long)(NP + NA) * 32), TB>>>(
        off_pp, srt_pp, es0, ed0, hs0,
        off_ap, srt_ap, es1, ed1, hs1,
        off_pa, srt_pa, es2, ed2, hs2,
        accp, acca, b1 + 0, b1 + 128, b1 + 256, 1);

    // ---------------- layer 2 (D=64) -> d_out ----------------
    {
        dim3 gP(1, (NP + 127) / 128), gA(1, (NA + 127) / 128);
        mma_es2<16><<<gP, 256>>>(accp, Wsrc2 + 0 * 128 * 64, Wsrc2 + 2 * 128 * 64,
                                 hs0b, hs2b, es0b, es2b, asrc2 + 0 * 64, asrc2 + 2 * 64,
                                 vd2 + 0 * 512, vd2 + 1 * 512, ed0b, ed1b, NP, 64);
        mma_es<16, 1><<<gA, 256>>>(acca, Wsrc2 + 1 * 128 * 64, hs1b, es1b, asrc2 + 1 * 64,
                                   vd2 + 2 * 512, nullptr, ed2b, nullptr, NA, 64);
        gat_gather_all<64><<<blocks((long long)(NP + NA) * 32), TB>>>(
            off_pp, srt_pp, es0b, ed0b, hs0b,
            off_ap, srt_ap, es1b, ed1b, hs1b,
            off_pa, srt_pa, es2b, ed2b, hs2b,
            out, out + (size_t)NP * 64, b2 + 0, b2 + 64, b2 + 128, 0);
    }
}